// round 9
// baseline (speedup 1.0000x reference)
#include <cuda_runtime.h>
#include <math.h>
#include <stdint.h>

#define CDIV(a,b) (((a)+(b)-1)/(b))

static constexpr int BB   = 32;
static constexpr int CINN = 128;
static constexpr int CO   = 256;
static constexpr int HWP  = 1024;          // 32*32
static constexpr int MTOT = BB * HWP;      // 32768
static constexpr int MEMN = 64;

// ---------------- scratch (static device memory; no allocations) ----------------
__device__ float g_xT   [(size_t)CINN * MTOT];        // x transposed  [128][M]
__device__ float g_t1   [(size_t)CO * MTOT];          // conv1 raw     [256][M]
__device__ float g_t2   [(size_t)CO * MTOT];          // conv2 raw
__device__ float g_id   [(size_t)CO * MTOT];          // shortcut conv raw
__device__ float g_h    [(size_t)CO * MTOT];          // ctrl hidden
__device__ float g_q    [(size_t)CO * MTOT];          // ctrl out (query)
__device__ float g_xfret[(size_t)512 * MTOT];         // [xfT(256) ; retT(256)][M]
__device__ float g_attn [(size_t)MEMN * MTOT];        // attn transposed [64][M]
__device__ float g_mo   [(size_t)CO * MTOT];          // memory out
__device__ float g_memT [CO * MEMN];                  // mem transposed [256][64]
__device__ float4 g_stats1 [CO * BB];
__device__ float4 g_stats2 [CO * BB];
__device__ float4 g_statsid[CO * BB];
__device__ float g_a1[CO], g_c1[CO], g_a2[CO], g_c2[CO], g_asc[CO], g_csc[CO];
__device__ float g_chatt[BB * CO];
__device__ float g_spmean[MTOT], g_spmax[MTOT], g_sa[MTOT];

// ---------------- tf32 helpers ----------------
__device__ __forceinline__ void cvt_hilo(float x, uint32_t& h, uint32_t& l) {
    uint32_t hb;
    asm("cvt.rna.tf32.f32 %0, %1;" : "=r"(hb) : "f"(x));
    float hf = __uint_as_float(hb);
    float lf = x - hf;
    uint32_t lb;
    asm("cvt.rna.tf32.f32 %0, %1;" : "=r"(lb) : "f"(lf));
    h = hb; l = lb;
}

#define MMA_TF32(Cv, Af, Bf)                                                     \
    asm volatile("mma.sync.aligned.m16n8k8.row.col.f32.tf32.tf32.f32 "           \
                 "{%0,%1,%2,%3},{%4,%5,%6,%7},{%8,%9},{%0,%1,%2,%3};"            \
                 : "+f"(Cv[0]), "+f"(Cv[1]), "+f"(Cv[2]), "+f"(Cv[3])            \
                 : "r"(Af[0]), "r"(Af[1]), "r"(Af[2]), "r"(Af[3]),               \
                   "r"(Bf[0]), "r"(Bf[1]));

// ---------------- transpose x: NCHW -> [ci][b*1024+p] ----------------
__global__ void k_transpose_x(const float* __restrict__ x) {
    int id = blockIdx.x * 256 + threadIdx.x;      // 32*128*1024 total
    float v = x[id];
    int p  = id & 1023;
    int ci = (id >> 10) & 127;
    int b  = id >> 17;
    g_xT[(size_t)ci * MTOT + b * HWP + p] = v;
}

// padded smem row stride; 132 mod 16 == 4 -> LDS.64 frag loads hit each
// bank-pair exactly twice (2-phase minimum).
static constexpr int SMS = 132;

// ======================= shared GEMM core (mma part) =========================
// Block tile 128(m) x 128(n) x 16(k). 8 warps: 2(m) x 4(n); warp tile 64x32.
// Smem element = uint2{tf32_hi, tf32_lo}.

__device__ __forceinline__ void mma_block(
    uint2 (&As)[16][SMS], uint2 (&Bs)[16][SMS],
    int wm, int wn, int gid, int tig, float (&c)[4][4][4]) {
#pragma unroll
    for (int ks = 0; ks < 2; ks++) {
        int kb = ks * 8;
        uint2 b0[4], b1[4];
#pragma unroll
        for (int j = 0; j < 4; j++) {
            int nc = wn + j * 8 + gid;
            b0[j] = Bs[kb + tig][nc];
            b1[j] = Bs[kb + tig + 4][nc];
        }
#pragma unroll
        for (int i = 0; i < 4; i++) {
            int mr = wm + i * 16;
            uint2 a0 = As[kb + tig][mr + gid];
            uint2 a1 = As[kb + tig][mr + gid + 8];
            uint2 a2 = As[kb + tig + 4][mr + gid];
            uint2 a3 = As[kb + tig + 4][mr + gid + 8];
            uint32_t afh[4] = {a0.x, a1.x, a2.x, a3.x};
            uint32_t afl[4] = {a0.y, a1.y, a2.y, a3.y};
#pragma unroll
            for (int j = 0; j < 4; j++) {
                uint32_t bfh[2] = {b0[j].x, b1[j].x};
                uint32_t bfl[2] = {b0[j].y, b1[j].y};
                MMA_TF32(c[i][j], afh, bfh);
                MMA_TF32(c[i][j], afh, bfl);
                MMA_TF32(c[i][j], afl, bfh);
            }
        }
    }
}

// store a float4 (4 consecutive m at one k) as interleaved hi/lo, 2x STS.128
__device__ __forceinline__ void st_hilo4(uint2 (&S)[16][SMS], int kk, int am, float4 v) {
    uint32_t h0, l0, h1, l1, h2, l2, h3, l3;
    cvt_hilo(v.x, h0, l0); cvt_hilo(v.y, h1, l1);
    cvt_hilo(v.z, h2, l2); cvt_hilo(v.w, h3, l3);
    uint4 p0 = make_uint4(h0, l0, h1, l1);
    uint4 p1 = make_uint4(h2, l2, h3, l3);
    *(uint4*)&S[kk][am]     = p0;
    *(uint4*)&S[kk][am + 2] = p1;
}

// ---------------- tensor-core GEMM (3xTF32): C[n][m] = sum_k A[k][m]*B[n][k] ------
// EPI: 0 = bias, 1 = bias+relu, 2 = gate epilogue (sigmoid(acc+bias); blend ret/xf)
template <int EPI>
__global__ void __launch_bounds__(256)
k_gemm_tc(const float* __restrict__ A, const float* __restrict__ Bw,
          const float* __restrict__ bias, float* __restrict__ C, int K,
          const float* __restrict__ e_xf, const float* __restrict__ e_ret) {
    __shared__ uint2 As[16][SMS], Bs[16][SMS];
    int tid = threadIdx.x;
    int m0 = blockIdx.x * 128, n0 = blockIdx.y * 128;
    int wid = tid >> 5, lane = tid & 31;
    int wm = (wid & 1) * 64;
    int wn = (wid >> 1) * 32;
    int gid = lane >> 2, tig = lane & 3;

    float c[4][4][4];
#pragma unroll
    for (int i = 0; i < 4; i++)
#pragma unroll
        for (int j = 0; j < 4; j++)
#pragma unroll
            for (int r = 0; r < 4; r++) c[i][j][r] = 0.f;

    int am = (tid & 31) * 4, ak = tid >> 5;    // A loader
    int bn = tid & 127, bk4 = (tid >> 7) * 4;  // B loader

    float4 rA[2], rB[2];
    // prologue: prefetch tile 0
#pragma unroll
    for (int s = 0; s < 2; s++) {
        rA[s] = *(const float4*)&A[(size_t)(ak + s * 8) * MTOT + m0 + am];
        rB[s] = *(const float4*)&Bw[(size_t)(n0 + bn) * K + bk4 + s * 8];
    }

    for (int k0 = 0; k0 < K; k0 += 16) {
        // ---- store stage (cvt + STS) ----
#pragma unroll
        for (int s = 0; s < 2; s++) {
            st_hilo4(As, ak + s * 8, am, rA[s]);
            int kq = bk4 + s * 8;
            float4 v = rB[s];
            uint32_t h, l;
            cvt_hilo(v.x, h, l); Bs[kq + 0][bn] = make_uint2(h, l);
            cvt_hilo(v.y, h, l); Bs[kq + 1][bn] = make_uint2(h, l);
            cvt_hilo(v.z, h, l); Bs[kq + 2][bn] = make_uint2(h, l);
            cvt_hilo(v.w, h, l); Bs[kq + 3][bn] = make_uint2(h, l);
        }
        __syncthreads();
        // ---- prefetch next tile (overlaps mma) ----
        int kn = k0 + 16;
        if (kn < K) {
#pragma unroll
            for (int s = 0; s < 2; s++) {
                rA[s] = *(const float4*)&A[(size_t)(kn + ak + s * 8) * MTOT + m0 + am];
                rB[s] = *(const float4*)&Bw[(size_t)(n0 + bn) * K + kn + bk4 + s * 8];
            }
        }
        mma_block(As, Bs, wm, wn, gid, tig, c);
        __syncthreads();
    }

#pragma unroll
    for (int i = 0; i < 4; i++) {
        int mlo = m0 + wm + i * 16 + gid;
#pragma unroll
        for (int j = 0; j < 4; j++) {
            int nlo = n0 + wn + j * 8 + 2 * tig;
            float b0 = bias ? bias[nlo] : 0.f;
            float b1 = bias ? bias[nlo + 1] : 0.f;
#pragma unroll
            for (int r = 0; r < 4; r++) {
                int n = nlo + (r & 1);
                int m = mlo + (r >> 1) * 8;
                float v = c[i][j][r] + ((r & 1) ? b1 : b0);
                if (EPI == 1) v = fmaxf(v, 0.f);
                if (EPI == 2) {
                    float g = 1.f / (1.f + expf(-v));
                    size_t off = (size_t)n * MTOT + m;
                    v = g * e_ret[off] + (1.f - g) * e_xf[off];
                }
                C[(size_t)n * MTOT + m] = v;
            }
        }
    }
}

// ---------------- implicit-GEMM conv (3x3, pad 1) on tensor cores ----------------
// A[k][m] gathered on the fly from src[ci][b*1024 + (h+dh)*32 + (w+dw)] with
// zero padding; k = ci*9 + (dh+1)*3 + (dw+1). ACT=1: fuse BN+ReLU of src.
template <int ACT>
__global__ void __launch_bounds__(256)
k_conv_tc(const float* __restrict__ src, const float* __restrict__ Bw,
          const float* __restrict__ bias, float* __restrict__ C, int K,
          const float* __restrict__ aa, const float* __restrict__ cc) {
    __shared__ uint2 As[16][SMS], Bs[16][SMS];
    int tid = threadIdx.x;
    int m0 = blockIdx.x * 128, n0 = blockIdx.y * 128;
    int wid = tid >> 5, lane = tid & 31;
    int wm = (wid & 1) * 64;
    int wn = (wid >> 1) * 32;
    int gid = lane >> 2, tig = lane & 3;

    float c[4][4][4];
#pragma unroll
    for (int i = 0; i < 4; i++)
#pragma unroll
        for (int j = 0; j < 4; j++)
#pragma unroll
            for (int r = 0; r < 4; r++) c[i][j][r] = 0.f;

    int am = (tid & 31) * 4, ak = tid >> 5;    // A loader: (kk, 4 m-elements)
    int bn = tid & 127, bk4 = (tid >> 7) * 4;  // B loader

    int pm = (m0 + am) & 1023;                 // batch-invariant image position
    int hbase = pm >> 5, wbase = pm & 31;

    // gather one k-row's 4 m-values (raw, pre-activation)
    auto gatherA = [&](int k, float (&v)[4], int& ci_out) {
        int ci = k / 9, r = k - ci * 9;
        int dh = r / 3 - 1, dw = r - (r / 3) * 3 - 1;
        int h  = hbase + dh;
        bool hok = (unsigned)h < 32u;
        const float* sp = src + (size_t)ci * MTOT + (m0 + am) + dh * 32 + dw;
#pragma unroll
        for (int e = 0; e < 4; e++) {
            int w = wbase + dw + e;
            v[e] = (hok && (unsigned)w < 32u) ? __ldg(sp + e) : 0.f;
        }
        ci_out = ci;
    };

    float vA[2][4]; int ciA[2];
    float4 rB[2];
#pragma unroll
    for (int s = 0; s < 2; s++) {
        gatherA(ak + s * 8, vA[s], ciA[s]);
        rB[s] = *(const float4*)&Bw[(size_t)(n0 + bn) * K + bk4 + s * 8];
    }

    for (int k0 = 0; k0 < K; k0 += 16) {
        // ---- store stage ----
#pragma unroll
        for (int s = 0; s < 2; s++) {
            float v0 = vA[s][0], v1 = vA[s][1], v2 = vA[s][2], v3 = vA[s][3];
            if (ACT) {
                float a = aa[ciA[s]], cbv = cc[ciA[s]];
                v0 = fmaxf(fmaf(a, v0, cbv), 0.f);
                v1 = fmaxf(fmaf(a, v1, cbv), 0.f);
                v2 = fmaxf(fmaf(a, v2, cbv), 0.f);
                v3 = fmaxf(fmaf(a, v3, cbv), 0.f);
            }
            st_hilo4(As, ak + s * 8, am, make_float4(v0, v1, v2, v3));
            int kq = bk4 + s * 8;
            float4 v = rB[s];
            uint32_t h, l;
            cvt_hilo(v.x, h, l); Bs[kq + 0][bn] = make_uint2(h, l);
            cvt_hilo(v.y, h, l); Bs[kq + 1][bn] = make_uint2(h, l);
            cvt_hilo(v.z, h, l); Bs[kq + 2][bn] = make_uint2(h, l);
            cvt_hilo(v.w, h, l); Bs[kq + 3][bn] = make_uint2(h, l);
        }
        __syncthreads();
        // ---- prefetch next tile (overlaps mma) ----
        int kn = k0 + 16;
        if (kn < K) {
#pragma unroll
            for (int s = 0; s < 2; s++) {
                gatherA(kn + ak + s * 8, vA[s], ciA[s]);
                rB[s] = *(const float4*)&Bw[(size_t)(n0 + bn) * K + kn + bk4 + s * 8];
            }
        }
        mma_block(As, Bs, wm, wn, gid, tig, c);
        __syncthreads();
    }

    // epilogue: bias only
#pragma unroll
    for (int i = 0; i < 4; i++) {
        int mlo = m0 + wm + i * 16 + gid;
#pragma unroll
        for (int j = 0; j < 4; j++) {
            int nlo = n0 + wn + j * 8 + 2 * tig;
            float b0 = bias[nlo], b1 = bias[nlo + 1];
#pragma unroll
            for (int r = 0; r < 4; r++) {
                int n = nlo + (r & 1);
                int m = mlo + (r >> 1) * 8;
                C[(size_t)n * MTOT + m] = c[i][j][r] + ((r & 1) ? b1 : b0);
            }
        }
    }
}

// ---------------- per-(c,b) reduction: sum, sumsq, max, min over 1024 ----------------
__global__ void __launch_bounds__(256) k_reduce_bc(const float* __restrict__ src,
                                                   float4* __restrict__ out) {
    int cb = blockIdx.x;
    const float* p = src + (size_t)cb * HWP;
    int tid = threadIdx.x;
    float v0 = p[tid], v1 = p[tid + 256], v2 = p[tid + 512], v3 = p[tid + 768];
    float s  = v0 + v1 + v2 + v3;
    float ss = v0 * v0 + v1 * v1 + v2 * v2 + v3 * v3;
    float mx = fmaxf(fmaxf(v0, v1), fmaxf(v2, v3));
    float mn = fminf(fminf(v0, v1), fminf(v2, v3));
#pragma unroll
    for (int o = 16; o; o >>= 1) {
        s  += __shfl_down_sync(0xffffffffu, s, o);
        ss += __shfl_down_sync(0xffffffffu, ss, o);
        mx = fmaxf(mx, __shfl_down_sync(0xffffffffu, mx, o));
        mn = fminf(mn, __shfl_down_sync(0xffffffffu, mn, o));
    }
    __shared__ float4 wred[8];
    int lane = tid & 31, wid = tid >> 5;
    if (lane == 0) wred[wid] = make_float4(s, ss, mx, mn);
    __syncthreads();
    if (tid == 0) {
        float4 r = wred[0];
        for (int i = 1; i < 8; i++) {
            r.x += wred[i].x; r.y += wred[i].y;
            r.z = fmaxf(r.z, wred[i].z); r.w = fminf(r.w, wred[i].w);
        }
        out[cb] = r;
    }
}

// ---------------- finalize BN coefficients per channel ----------------
__global__ void k_bn_coeffs(const float4* __restrict__ stats,
                            const float* __restrict__ g, const float* __restrict__ beta,
                            float* __restrict__ a, float* __restrict__ c) {
    int ch = threadIdx.x;     // <<<1,256>>>
    float s = 0.f, ss = 0.f;
    for (int b = 0; b < BB; b++) { float4 v = stats[ch * BB + b]; s += v.x; ss += v.y; }
    float mean = s * (1.f / 32768.f);
    float var  = ss * (1.f / 32768.f) - mean * mean;
    float av = g[ch] * rsqrtf(var + 1e-5f);
    a[ch] = av;
    c[ch] = beta[ch] - av * mean;
}

// ---------------- channel attention MLP ----------------
__global__ void __launch_bounds__(256) k_ca_mlp(const float* __restrict__ w1,
                                                const float* __restrict__ w2) {
    int b = blockIdx.x, tid = threadIdx.x;
    __shared__ float va[CO], vm[CO], hsum[16];
    {
        float4 st = g_stats2[tid * BB + b];
        float a = g_a2[tid], c = g_c2[tid];
        va[tid] = a * st.x * (1.f / 1024.f) + c;
        vm[tid] = (a >= 0.f ? a * st.z : a * st.w) + c;
    }
    __syncthreads();
    int wid = tid >> 5, lane = tid & 31;
    for (int u = 0; u < 2; u++) {
        int j = wid * 2 + u;
        float sa = 0.f, sm = 0.f;
        for (int c = lane; c < CO; c += 32) {
            float wv = w1[j * CO + c];
            sa += wv * va[c]; sm += wv * vm[c];
        }
#pragma unroll
        for (int o = 16; o; o >>= 1) {
            sa += __shfl_down_sync(0xffffffffu, sa, o);
            sm += __shfl_down_sync(0xffffffffu, sm, o);
        }
        if (lane == 0) hsum[j] = fmaxf(sa, 0.f) + fmaxf(sm, 0.f);
    }
    __syncthreads();
    float s = 0.f;
    for (int j = 0; j < 16; j++) s += hsum[j] * w2[tid * 16 + j];
    g_chatt[b * CO + tid] = 1.f / (1.f + expf(-s));
}

// ---------------- spatial pooling over channels (mean & max) ----------------
__global__ void __launch_bounds__(256) k_sp_pool() {
    int m = blockIdx.x * 256 + threadIdx.x;
    int b = m >> 10;
    __shared__ float co[CO], of[CO];
    {
        int t = threadIdx.x;
        float ca = g_chatt[b * CO + t];
        co[t] = ca * g_a2[t];
        of[t] = ca * g_c2[t];
    }
    __syncthreads();
    float s = 0.f, mx = -1e30f;
    for (int c = 0; c < CO; c++) {
        float v = fmaf(co[c], g_t2[(size_t)c * MTOT + m], of[c]);
        s += v; mx = fmaxf(mx, v);
    }
    g_spmean[m] = s * (1.f / 256.f);
    g_spmax[m]  = mx;
}

// ---------------- spatial attention 7x7 conv + sigmoid ----------------
__global__ void __launch_bounds__(1024) k_sa_conv(const float* __restrict__ sw,
                                                  const float* __restrict__ sb) {
    int b = blockIdx.x, p = threadIdx.x;
    __shared__ float me[HWP], ma[HWP];
    me[p] = g_spmean[b * HWP + p];
    ma[p] = g_spmax[b * HWP + p];
    __syncthreads();
    int h = p >> 5, w = p & 31;
    float acc = sb[0];
#pragma unroll
    for (int kh = 0; kh < 7; kh++) {
        int hh = h + kh - 3;
        if ((unsigned)hh >= 32u) continue;
#pragma unroll
        for (int kw = 0; kw < 7; kw++) {
            int ww = w + kw - 3;
            if ((unsigned)ww >= 32u) continue;
            int q = hh * 32 + ww;
            acc += sw[kh * 7 + kw] * me[q] + sw[49 + kh * 7 + kw] * ma[q];
        }
    }
    g_sa[b * HWP + p] = 1.f / (1.f + expf(-acc));
}

// ---------------- build xf (post channel+spatial attention), T layout ----------------
__global__ void k_build_xf() {
    int c = blockIdx.y;
    int m = blockIdx.x * 256 + threadIdx.x;
    int b = m >> 10;
    float ca = g_chatt[b * CO + c];
    float v = ca * fmaf(g_a2[c], g_t2[(size_t)c * MTOT + m], g_c2[c]) * g_sa[m];
    g_xfret[(size_t)c * MTOT + m] = v;
}

// ---------------- mem transpose [64][256] -> [256][64] ----------------
__global__ void k_mem_t(const float* __restrict__ mem) {
    int id = blockIdx.x * 256 + threadIdx.x;   // 16384
    int j = id >> 8, n = id & 255;
    g_memT[n * MEMN + j] = mem[id];
}

// ---------------- logits + softmax (rows of 64), writes attnT [64][M] ----------------
__global__ void __launch_bounds__(256) k_logits_softmax(const float* __restrict__ keys) {
    __shared__ float qs[16][128];
    __shared__ float ks[16][64];
    __shared__ float red[128][8];
    __shared__ float rowred[128];
    int tid = threadIdx.x;
    int m0 = blockIdx.x * 128;
    float acc[4][8];
#pragma unroll
    for (int i = 0; i < 4; i++)
#pragma unroll
        for (int j = 0; j < 8; j++) acc[i][j] = 0.f;
    int m4 = tid & 31, kr = tid >> 5;
    int jb = tid & 63, kq = tid >> 6;
    int tx = tid & 7, ty = tid >> 3;
    for (int k0 = 0; k0 < 256; k0 += 16) {
#pragma unroll
        for (int s = 0; s < 2; s++) {
            int kk = kr + s * 8;
            *(float4*)&qs[kk][m4 * 4] =
                *(const float4*)&g_q[(size_t)(k0 + kk) * MTOT + m0 + m4 * 4];
        }
        {
            float4 v = *(const float4*)&keys[jb * 256 + k0 + kq * 4];
            ks[kq * 4 + 0][jb] = v.x; ks[kq * 4 + 1][jb] = v.y;
            ks[kq * 4 + 2][jb] = v.z; ks[kq * 4 + 3][jb] = v.w;
        }
        __syncthreads();
#pragma unroll
        for (int kk = 0; kk < 16; kk++) {
            float a[4], b[8];
#pragma unroll
            for (int i = 0; i < 4; i++) a[i] = qs[kk][ty * 4 + i];
#pragma unroll
            for (int j = 0; j < 8; j++) b[j] = ks[kk][tx * 8 + j];
#pragma unroll
            for (int i = 0; i < 4; i++)
#pragma unroll
                for (int j = 0; j < 8; j++) acc[i][j] = fmaf(a[i], b[j], acc[i][j]);
        }
        __syncthreads();
    }
    const float sc = 0.0625f;   // 1/sqrt(256)
#pragma unroll
    for (int i = 0; i < 4; i++) {
        float mx = -1e30f;
#pragma unroll
        for (int j = 0; j < 8; j++) { acc[i][j] *= sc; mx = fmaxf(mx, acc[i][j]); }
        red[ty * 4 + i][tx] = mx;
    }
    __syncthreads();
    if (tid < 128) {
        float mx = -1e30f;
        for (int t = 0; t < 8; t++) mx = fmaxf(mx, red[tid][t]);
        rowred[tid] = mx;
    }
    __syncthreads();
#pragma unroll
    for (int i = 0; i < 4; i++) {
        float rm = rowred[ty * 4 + i], s = 0.f;
#pragma unroll
        for (int j = 0; j < 8; j++) { acc[i][j] = expf(acc[i][j] - rm); s += acc[i][j]; }
        red[ty * 4 + i][tx] = s;
    }
    __syncthreads();
    if (tid < 128) {
        float s = 0.f;
        for (int t = 0; t < 8; t++) s += red[tid][t];
        rowred[tid] = 1.f / s;
    }
    __syncthreads();
#pragma unroll
    for (int i = 0; i < 4; i++) {
        float inv = rowred[ty * 4 + i];
#pragma unroll
        for (int j = 0; j < 8; j++)
            g_attn[(size_t)(tx * 8 + j) * MTOT + m0 + ty * 4 + i] = acc[i][j] * inv;
    }
}

// ---------------- final: spike + BN(shortcut) + relu, write NCHW ----------------
__global__ void k_final(float* __restrict__ out) {
    int c = blockIdx.y;
    int m = blockIdx.x * 256 + threadIdx.x;
    float mo = g_mo[(size_t)c * MTOT + m];
    float spike = (0.1f * mo >= 1.0f) ? 1.f : 0.f;
    float idv = fmaf(g_asc[c], g_id[(size_t)c * MTOT + m], g_csc[c]);
    int b = m >> 10, p = m & 1023;
    out[(size_t)b * CO * HWP + c * HWP + p] = fmaxf(spike + idv, 0.f);
}

// =============================== host launcher ===============================
extern "C" void kernel_launch(void* const* d_in, const int* in_sizes, int n_in,
                              void* d_out, int out_size) {
    const float* x       = (const float*)d_in[0];
    const float* conv1_w = (const float*)d_in[1];
    const float* conv1_b = (const float*)d_in[2];
    const float* bn1_g   = (const float*)d_in[3];
    const float* bn1_b   = (const float*)d_in[4];
    const float* conv2_w = (const float*)d_in[5];
    const float* conv2_b = (const float*)d_in[6];
    const float* bn2_g   = (const float*)d_in[7];
    const float* bn2_b   = (const float*)d_in[8];
    const float* ca_w1   = (const float*)d_in[9];
    const float* ca_w2   = (const float*)d_in[10];
    const float* sa_w    = (const float*)d_in[11];
    const float* sa_b    = (const float*)d_in[12];
    const float* memp    = (const float*)d_in[13];
    const float* mem_keys= (const float*)d_in[14];
    const float* ctrl_w1 = (const float*)d_in[15];
    const float* ctrl_b1 = (const float*)d_in[16];
    const float* ctrl_w2 = (const float*)d_in[17];
    const float* ctrl_b2 = (const float*)d_in[18];
    const float* gate_w  = (const float*)d_in[19];
    const float* gate_b  = (const float*)d_in[20];
    const float* sc_w    = (const float*)d_in[21];
    const float* sc_g    = (const float*)d_in[22];
    const float* sc_b    = (const float*)d_in[23];

    float *xT, *t1, *t2, *idb, *hb, *qb, *xfret, *attn, *mo, *memT;
    float *a1, *c1, *a2, *c2, *asc, *csc;
    float4 *st1, *st2, *stid;
    cudaGetSymbolAddress((void**)&xT, g_xT);
    cudaGetSymbolAddress((void**)&t1, g_t1);
    cudaGetSymbolAddress((void**)&t2, g_t2);
    cudaGetSymbolAddress((void**)&idb, g_id);
    cudaGetSymbolAddress((void**)&hb, g_h);
    cudaGetSymbolAddress((void**)&qb, g_q);
    cudaGetSymbolAddress((void**)&xfret, g_xfret);
    cudaGetSymbolAddress((void**)&attn, g_attn);
    cudaGetSymbolAddress((void**)&mo, g_mo);
    cudaGetSymbolAddress((void**)&memT, g_memT);
    cudaGetSymbolAddress((void**)&a1, g_a1);
    cudaGetSymbolAddress((void**)&c1, g_c1);
    cudaGetSymbolAddress((void**)&a2, g_a2);
    cudaGetSymbolAddress((void**)&c2, g_c2);
    cudaGetSymbolAddress((void**)&asc, g_asc);
    cudaGetSymbolAddress((void**)&csc, g_csc);
    cudaGetSymbolAddress((void**)&st1, g_stats1);
    cudaGetSymbolAddress((void**)&st2, g_stats2);
    cudaGetSymbolAddress((void**)&stid, g_statsid);

    dim3 gemm_grid(MTOT / 128, 2);   // N = 256 always

    // 1) transpose input
    k_transpose_x<<<BB * CINN * HWP / 256, 256>>>(x);

    // 2) shortcut conv (1x1): plain GEMM K=128
    k_gemm_tc<0><<<gemm_grid, 256>>>(xT, sc_w, nullptr, idb, 128, nullptr, nullptr);
    k_reduce_bc<<<CO * BB, 256>>>(idb, stid);
    k_bn_coeffs<<<1, 256>>>(stid, sc_g, sc_b, asc, csc);

    // 3) conv1: implicit-GEMM (K=1152) straight from xT
    k_conv_tc<0><<<gemm_grid, 256>>>(xT, conv1_w, conv1_b, t1, CINN * 9,
                                     nullptr, nullptr);
    k_reduce_bc<<<CO * BB, 256>>>(t1, st1);
    k_bn_coeffs<<<1, 256>>>(st1, bn1_g, bn1_b, a1, c1);

    // 4) conv2: implicit-GEMM (K=2304) with fused BN1+ReLU in the gather
    k_conv_tc<1><<<gemm_grid, 256>>>(t1, conv2_w, conv2_b, t2, CO * 9, a1, c1);
    k_reduce_bc<<<CO * BB, 256>>>(t2, st2);
    k_bn_coeffs<<<1, 256>>>(st2, bn2_g, bn2_b, a2, c2);

    // 5) channel attention (uses per-(b,c) stats of t2)
    k_ca_mlp<<<BB, 256>>>(ca_w1, ca_w2);

    // 6) spatial attention
    k_sp_pool<<<MTOT / 256, 256>>>();
    k_sa_conv<<<BB, 1024>>>(sa_w, sa_b);

    // 7) xf (attention-applied features) into front half of xfret buffer
    k_build_xf<<<dim3(MTOT / 256, CO), 256>>>();

    // 8) memory module
    k_gemm_tc<1><<<gemm_grid, 256>>>(xfret, ctrl_w1, ctrl_b1, hb, 256, nullptr, nullptr);
    k_gemm_tc<0><<<gemm_grid, 256>>>(hb, ctrl_w2, ctrl_b2, qb, 256, nullptr, nullptr);
    k_mem_t<<<MEMN * CO / 256, 256>>>(memp);
    k_logits_softmax<<<MTOT / 128, 256>>>(mem_keys);
    k_gemm_tc<0><<<gemm_grid, 256>>>(attn, memT, nullptr, xfret + (size_t)256 * MTOT,
                                     MEMN, nullptr, nullptr);
    k_gemm_tc<2><<<gemm_grid, 256>>>(xfret, gate_w, gate_b, mo, 512,
                                     xfret, xfret + (size_t)256 * MTOT);

    // 9) spike + shortcut + relu -> NCHW output
    k_final<<<dim3(MTOT / 256, CO), 256>>>((float*)d_out);
}

// round 13
// speedup vs baseline: 2.0664x; 2.0664x over previous
#include <cuda_runtime.h>
#include <math.h>
#include <stdint.h>

#define CDIV(a,b) (((a)+(b)-1)/(b))

static constexpr int BB   = 32;
static constexpr int CINN = 128;
static constexpr int CO   = 256;
static constexpr int HWP  = 1024;          // 32*32
static constexpr int MTOT = BB * HWP;      // 32768
static constexpr int MEMN = 64;

// ---------------- scratch (static device memory; no allocations) ----------------
__device__ float g_xT   [(size_t)CINN * MTOT];        // x transposed  [128][M]
__device__ float g_t1   [(size_t)CO * MTOT];          // conv1 raw     [256][M]
__device__ float g_t2   [(size_t)CO * MTOT];          // conv2 raw
__device__ float g_id   [(size_t)CO * MTOT];          // shortcut conv raw
__device__ float g_h    [(size_t)CO * MTOT];          // ctrl hidden
__device__ float g_q    [(size_t)CO * MTOT];          // ctrl out (query)
__device__ float g_xfret[(size_t)512 * MTOT];         // [xfT(256) ; retT(256)][M]
__device__ float g_attn [(size_t)MEMN * MTOT];        // attn transposed [64][M]
__device__ float g_mo   [(size_t)CO * MTOT];          // memory out
__device__ float g_memT [CO * MEMN];                  // mem transposed [256][64]
__device__ float4 g_stats2 [CO * BB];                 // conv2 per-(c,b) stats (for CA)
__device__ float g_a1[CO], g_c1[CO], g_a2[CO], g_c2[CO], g_asc[CO], g_csc[CO];
__device__ float g_chatt[BB * CO];
__device__ float g_spmean[MTOT], g_spmax[MTOT], g_sa[MTOT];

// ---------------- tf32 helpers ----------------
__device__ __forceinline__ void cvt_hilo(float x, uint32_t& h, uint32_t& l) {
    uint32_t hb;
    asm("cvt.rna.tf32.f32 %0, %1;" : "=r"(hb) : "f"(x));
    float hf = __uint_as_float(hb);
    float lf = x - hf;
    uint32_t lb;
    asm("cvt.rna.tf32.f32 %0, %1;" : "=r"(lb) : "f"(lf));
    h = hb; l = lb;
}

#define MMA_TF32(Cv, Af, Bf)                                                     \
    asm volatile("mma.sync.aligned.m16n8k8.row.col.f32.tf32.tf32.f32 "           \
                 "{%0,%1,%2,%3},{%4,%5,%6,%7},{%8,%9},{%0,%1,%2,%3};"            \
                 : "+f"(Cv[0]), "+f"(Cv[1]), "+f"(Cv[2]), "+f"(Cv[3])            \
                 : "r"(Af[0]), "r"(Af[1]), "r"(Af[2]), "r"(Af[3]),               \
                   "r"(Bf[0]), "r"(Bf[1]));

// ---------------- transpose x: NCHW -> [ci][b*1024+p] ----------------
__global__ void k_transpose_x(const float* __restrict__ x) {
    int id = blockIdx.x * 256 + threadIdx.x;      // 32*128*1024 total
    float v = x[id];
    int p  = id & 1023;
    int ci = (id >> 10) & 127;
    int b  = id >> 17;
    g_xT[(size_t)ci * MTOT + b * HWP + p] = v;
}

static constexpr int SMS = 136;   // padded smem row stride (conflict-free frag loads)

// ======================= shared GEMM core (mma part) =========================
// Block tile 128(m) x 128(n) x 16(k). 8 warps: 2(m) x 4(n); warp tile 64x32.

__device__ __forceinline__ void mma_block(
    uint32_t (&Ah)[16][SMS], uint32_t (&Al)[16][SMS],
    uint32_t (&Bh)[16][SMS], uint32_t (&Bl)[16][SMS],
    int wm, int wn, int gid, int tig, float (&c)[4][4][4]) {
#pragma unroll
    for (int ks = 0; ks < 2; ks++) {
        int kb = ks * 8;
        uint32_t bfh[4][2], bfl[4][2];
#pragma unroll
        for (int j = 0; j < 4; j++) {
            int nc = wn + j * 8 + gid;
            bfh[j][0] = Bh[kb + tig][nc];
            bfh[j][1] = Bh[kb + tig + 4][nc];
            bfl[j][0] = Bl[kb + tig][nc];
            bfl[j][1] = Bl[kb + tig + 4][nc];
        }
#pragma unroll
        for (int i = 0; i < 4; i++) {
            int mr = wm + i * 16;
            uint32_t afh[4], afl[4];
            afh[0] = Ah[kb + tig][mr + gid];
            afh[1] = Ah[kb + tig][mr + gid + 8];
            afh[2] = Ah[kb + tig + 4][mr + gid];
            afh[3] = Ah[kb + tig + 4][mr + gid + 8];
            afl[0] = Al[kb + tig][mr + gid];
            afl[1] = Al[kb + tig][mr + gid + 8];
            afl[2] = Al[kb + tig + 4][mr + gid];
            afl[3] = Al[kb + tig + 4][mr + gid + 8];
#pragma unroll
            for (int j = 0; j < 4; j++) {
                MMA_TF32(c[i][j], afh, bfh[j]);
                MMA_TF32(c[i][j], afh, bfl[j]);
                MMA_TF32(c[i][j], afl, bfh[j]);
            }
        }
    }
}

__device__ __forceinline__ void stA_hilo(uint32_t (&Ah)[16][SMS], uint32_t (&Al)[16][SMS],
                                         int kk, int am, float4 v) {
    uint4 h, l;
    cvt_hilo(v.x, h.x, l.x); cvt_hilo(v.y, h.y, l.y);
    cvt_hilo(v.z, h.z, l.z); cvt_hilo(v.w, h.w, l.w);
    *(uint4*)&Ah[kk][am] = h;
    *(uint4*)&Al[kk][am] = l;
}

__device__ __forceinline__ void stB_hilo(uint32_t (&Bh)[16][SMS], uint32_t (&Bl)[16][SMS],
                                         int kq, int bn, float4 v) {
    uint32_t h, l;
    cvt_hilo(v.x, h, l); Bh[kq + 0][bn] = h; Bl[kq + 0][bn] = l;
    cvt_hilo(v.y, h, l); Bh[kq + 1][bn] = h; Bl[kq + 1][bn] = l;
    cvt_hilo(v.z, h, l); Bh[kq + 2][bn] = h; Bl[kq + 2][bn] = l;
    cvt_hilo(v.w, h, l); Bh[kq + 3][bn] = h; Bl[kq + 3][bn] = l;
}

// ---------------- tensor-core GEMM (3xTF32): C[n][m] = sum_k A[k][m]*B[n][k] ------
// EPI: 0 = bias, 1 = bias+relu, 2 = gate epilogue (sigmoid(acc+bias); blend ret/xf)
template <int EPI>
__global__ void __launch_bounds__(256, 2)
k_gemm_tc(const float* __restrict__ A, const float* __restrict__ Bw,
          const float* __restrict__ bias, float* __restrict__ C, int K,
          const float* __restrict__ e_xf, const float* __restrict__ e_ret) {
    __shared__ uint32_t Ah[16][SMS], Al[16][SMS], Bh[16][SMS], Bl[16][SMS];
    int tid = threadIdx.x;
    int m0 = blockIdx.x * 128, n0 = blockIdx.y * 128;
    int wid = tid >> 5, lane = tid & 31;
    int wm = (wid & 1) * 64;
    int wn = (wid >> 1) * 32;
    int gid = lane >> 2, tig = lane & 3;

    float c[4][4][4];
#pragma unroll
    for (int i = 0; i < 4; i++)
#pragma unroll
        for (int j = 0; j < 4; j++)
#pragma unroll
            for (int r = 0; r < 4; r++) c[i][j][r] = 0.f;

    int am = (tid & 31) * 4, ak = tid >> 5;    // A loader
    int bn = tid & 127, bk4 = (tid >> 7) * 4;  // B loader

    float4 rA[2], rB[2];
#pragma unroll
    for (int s = 0; s < 2; s++) {
        rA[s] = *(const float4*)&A[(size_t)(ak + s * 8) * MTOT + m0 + am];
        rB[s] = *(const float4*)&Bw[(size_t)(n0 + bn) * K + bk4 + s * 8];
    }

    for (int k0 = 0; k0 < K; k0 += 16) {
#pragma unroll
        for (int s = 0; s < 2; s++) {
            stA_hilo(Ah, Al, ak + s * 8, am, rA[s]);
            stB_hilo(Bh, Bl, bk4 + s * 8, bn, rB[s]);
        }
        __syncthreads();
        int kn = k0 + 16;
        if (kn < K) {
#pragma unroll
            for (int s = 0; s < 2; s++) {
                rA[s] = *(const float4*)&A[(size_t)(kn + ak + s * 8) * MTOT + m0 + am];
                rB[s] = *(const float4*)&Bw[(size_t)(n0 + bn) * K + kn + bk4 + s * 8];
            }
        }
        mma_block(Ah, Al, Bh, Bl, wm, wn, gid, tig, c);
        __syncthreads();
    }

#pragma unroll
    for (int i = 0; i < 4; i++) {
        int mlo = m0 + wm + i * 16 + gid;
#pragma unroll
        for (int j = 0; j < 4; j++) {
            int nlo = n0 + wn + j * 8 + 2 * tig;
            float b0 = bias ? bias[nlo] : 0.f;
            float b1 = bias ? bias[nlo + 1] : 0.f;
#pragma unroll
            for (int r = 0; r < 4; r++) {
                int n = nlo + (r & 1);
                int m = mlo + (r >> 1) * 8;
                float v = c[i][j][r] + ((r & 1) ? b1 : b0);
                if (EPI == 1) v = fmaxf(v, 0.f);
                if (EPI == 2) {
                    float g = 1.f / (1.f + expf(-v));
                    size_t off = (size_t)n * MTOT + m;
                    v = g * e_ret[off] + (1.f - g) * e_xf[off];
                }
                C[(size_t)n * MTOT + m] = v;
            }
        }
    }
}

// ---------------- implicit-GEMM conv (3x3, pad 1) on tensor cores ----------------
// A[k][m] gathered on the fly from src[ci][b*1024 + (h+dh)*32 + (w+dw)] with
// zero padding; k = ci*9 + (dh+1)*3 + (dw+1). ACT=1: fuse BN+ReLU of src.
template <int ACT>
__global__ void __launch_bounds__(256, 2)
k_conv_tc(const float* __restrict__ src, const float* __restrict__ Bw,
          const float* __restrict__ bias, float* __restrict__ C, int K,
          const float* __restrict__ aa, const float* __restrict__ cc) {
    __shared__ uint32_t Ah[16][SMS], Al[16][SMS], Bh[16][SMS], Bl[16][SMS];
    int tid = threadIdx.x;
    int m0 = blockIdx.x * 128, n0 = blockIdx.y * 128;
    int wid = tid >> 5, lane = tid & 31;
    int wm = (wid & 1) * 64;
    int wn = (wid >> 1) * 32;
    int gid = lane >> 2, tig = lane & 3;

    float c[4][4][4];
#pragma unroll
    for (int i = 0; i < 4; i++)
#pragma unroll
        for (int j = 0; j < 4; j++)
#pragma unroll
            for (int r = 0; r < 4; r++) c[i][j][r] = 0.f;

    int am = (tid & 31) * 4, ak = tid >> 5;    // A loader: (kk, 4 m-elements)
    int bn = tid & 127, bk4 = (tid >> 7) * 4;  // B loader

    int pm = (m0 + am) & 1023;                 // batch-invariant image position
    int hbase = pm >> 5, wbase = pm & 31;

    auto gatherA = [&](int k, float (&v)[4], int& ci_out) {
        int ci = k / 9, r = k - ci * 9;
        int dh = r / 3 - 1, dw = r - (r / 3) * 3 - 1;
        int h  = hbase + dh;
        bool hok = (unsigned)h < 32u;
        const float* sp = src + (size_t)ci * MTOT + (m0 + am) + dh * 32 + dw;
#pragma unroll
        for (int e = 0; e < 4; e++) {
            int w = wbase + dw + e;
            v[e] = (hok && (unsigned)w < 32u) ? __ldg(sp + e) : 0.f;
        }
        ci_out = ci;
    };

    float vA[2][4]; int ciA[2];
    float4 rB[2];
#pragma unroll
    for (int s = 0; s < 2; s++) {
        gatherA(ak + s * 8, vA[s], ciA[s]);
        rB[s] = *(const float4*)&Bw[(size_t)(n0 + bn) * K + bk4 + s * 8];
    }

    for (int k0 = 0; k0 < K; k0 += 16) {
#pragma unroll
        for (int s = 0; s < 2; s++) {
            float v0 = vA[s][0], v1 = vA[s][1], v2 = vA[s][2], v3 = vA[s][3];
            if (ACT) {
                float a = aa[ciA[s]], cbv = cc[ciA[s]];
                v0 = fmaxf(fmaf(a, v0, cbv), 0.f);
                v1 = fmaxf(fmaf(a, v1, cbv), 0.f);
                v2 = fmaxf(fmaf(a, v2, cbv), 0.f);
                v3 = fmaxf(fmaf(a, v3, cbv), 0.f);
            }
            stA_hilo(Ah, Al, ak + s * 8, am, make_float4(v0, v1, v2, v3));
            stB_hilo(Bh, Bl, bk4 + s * 8, bn, rB[s]);
        }
        __syncthreads();
        int kn = k0 + 16;
        if (kn < K) {
#pragma unroll
            for (int s = 0; s < 2; s++) {
                gatherA(kn + ak + s * 8, vA[s], ciA[s]);
                rB[s] = *(const float4*)&Bw[(size_t)(n0 + bn) * K + kn + bk4 + s * 8];
            }
        }
        mma_block(Ah, Al, Bh, Bl, wm, wn, gid, tig, c);
        __syncthreads();
    }

#pragma unroll
    for (int i = 0; i < 4; i++) {
        int mlo = m0 + wm + i * 16 + gid;
#pragma unroll
        for (int j = 0; j < 4; j++) {
            int nlo = n0 + wn + j * 8 + 2 * tig;
            float b0 = bias[nlo], b1 = bias[nlo + 1];
#pragma unroll
            for (int r = 0; r < 4; r++) {
                int n = nlo + (r & 1);
                int m = mlo + (r >> 1) * 8;
                C[(size_t)n * MTOT + m] = c[i][j][r] + ((r & 1) ? b1 : b0);
            }
        }
    }
}

// ------- fused per-channel reduction + BN coeffs (one block per channel) -------
// Per batch-segment stats (sum,sumsq,max,min over 1024), optional store to
// g_stats2; channel totals -> BN coefficients a,c.
template <int STORE_STATS>
__global__ void __launch_bounds__(256) k_reduce_coeffs(
    const float* __restrict__ src, const float* __restrict__ g,
    const float* __restrict__ beta, float* __restrict__ a, float* __restrict__ cc) {
    int ch = blockIdx.x;
    int tid = threadIdx.x;
    int lane = tid & 31, wrp = tid >> 5;
    __shared__ float4 wred[8];
    __shared__ float tot[2];
    if (tid == 0) { tot[0] = 0.f; tot[1] = 0.f; }
    for (int b = 0; b < BB; b++) {
        const float* p = src + (size_t)(ch * BB + b) * HWP;
        float v0 = p[tid], v1 = p[tid + 256], v2 = p[tid + 512], v3 = p[tid + 768];
        float s  = v0 + v1 + v2 + v3;
        float ss = v0 * v0 + v1 * v1 + v2 * v2 + v3 * v3;
        float mx = fmaxf(fmaxf(v0, v1), fmaxf(v2, v3));
        float mn = fminf(fminf(v0, v1), fminf(v2, v3));
#pragma unroll
        for (int o = 16; o; o >>= 1) {
            s  += __shfl_down_sync(0xffffffffu, s, o);
            ss += __shfl_down_sync(0xffffffffu, ss, o);
            mx = fmaxf(mx, __shfl_down_sync(0xffffffffu, mx, o));
            mn = fminf(mn, __shfl_down_sync(0xffffffffu, mn, o));
        }
        if (lane == 0) wred[wrp] = make_float4(s, ss, mx, mn);
        __syncthreads();
        if (tid == 0) {
            float4 r = wred[0];
            for (int i = 1; i < 8; i++) {
                r.x += wred[i].x; r.y += wred[i].y;
                r.z = fmaxf(r.z, wred[i].z); r.w = fminf(r.w, wred[i].w);
            }
            if (STORE_STATS) g_stats2[ch * BB + b] = r;
            tot[0] += r.x; tot[1] += r.y;
        }
        __syncthreads();
    }
    if (tid == 0) {
        float mean = tot[0] * (1.f / 32768.f);
        float var  = tot[1] * (1.f / 32768.f) - mean * mean;
        float av = g[ch] * rsqrtf(var + 1e-5f);
        a[ch] = av;
        cc[ch] = beta[ch] - av * mean;
    }
}

// ---------------- channel attention MLP ----------------
__global__ void __launch_bounds__(256) k_ca_mlp(const float* __restrict__ w1,
                                                const float* __restrict__ w2) {
    int b = blockIdx.x, tid = threadIdx.x;
    __shared__ float va[CO], vm[CO], hsum[16];
    {
        float4 st = g_stats2[tid * BB + b];
        float a = g_a2[tid], c = g_c2[tid];
        va[tid] = a * st.x * (1.f / 1024.f) + c;
        vm[tid] = (a >= 0.f ? a * st.z : a * st.w) + c;
    }
    __syncthreads();
    int wid = tid >> 5, lane = tid & 31;
    for (int u = 0; u < 2; u++) {
        int j = wid * 2 + u;
        float sa = 0.f, sm = 0.f;
        for (int c = lane; c < CO; c += 32) {
            float wv = w1[j * CO + c];
            sa += wv * va[c]; sm += wv * vm[c];
        }
#pragma unroll
        for (int o = 16; o; o >>= 1) {
            sa += __shfl_down_sync(0xffffffffu, sa, o);
            sm += __shfl_down_sync(0xffffffffu, sm, o);
        }
        if (lane == 0) hsum[j] = fmaxf(sa, 0.f) + fmaxf(sm, 0.f);
    }
    __syncthreads();
    float s = 0.f;
    for (int j = 0; j < 16; j++) s += hsum[j] * w2[tid * 16 + j];
    g_chatt[b * CO + tid] = 1.f / (1.f + expf(-s));
}

// ---------------- spatial pooling over channels (mean & max) ----------------
__global__ void __launch_bounds__(256) k_sp_pool() {
    int m = blockIdx.x * 256 + threadIdx.x;
    int b = m >> 10;
    __shared__ float co[CO], of[CO];
    {
        int t = threadIdx.x;
        float ca = g_chatt[b * CO + t];
        co[t] = ca * g_a2[t];
        of[t] = ca * g_c2[t];
    }
    __syncthreads();
    float s = 0.f, mx = -1e30f;
    for (int c = 0; c < CO; c++) {
        float v = fmaf(co[c], g_t2[(size_t)c * MTOT + m], of[c]);
        s += v; mx = fmaxf(mx, v);
    }
    g_spmean[m] = s * (1.f / 256.f);
    g_spmax[m]  = mx;
}

// ---------------- spatial attention 7x7 conv + sigmoid ----------------
__global__ void __launch_bounds__(1024) k_sa_conv(const float* __restrict__ sw,
                                                  const float* __restrict__ sb) {
    int b = blockIdx.x, p = threadIdx.x;
    __shared__ float me[HWP], ma[HWP];
    me[p] = g_spmean[b * HWP + p];
    ma[p] = g_spmax[b * HWP + p];
    __syncthreads();
    int h = p >> 5, w = p & 31;
    float acc = sb[0];
#pragma unroll
    for (int kh = 0; kh < 7; kh++) {
        int hh = h + kh - 3;
        if ((unsigned)hh >= 32u) continue;
#pragma unroll
        for (int kw = 0; kw < 7; kw++) {
            int ww = w + kw - 3;
            if ((unsigned)ww >= 32u) continue;
            int q = hh * 32 + ww;
            acc += sw[kh * 7 + kw] * me[q] + sw[49 + kh * 7 + kw] * ma[q];
        }
    }
    g_sa[b * HWP + p] = 1.f / (1.f + expf(-acc));
}

// ---------------- build xf (post channel+spatial attention), T layout ----------------
__global__ void k_build_xf() {
    int c = blockIdx.y;
    int m = blockIdx.x * 256 + threadIdx.x;
    int b = m >> 10;
    float ca = g_chatt[b * CO + c];
    float v = ca * fmaf(g_a2[c], g_t2[(size_t)c * MTOT + m], g_c2[c]) * g_sa[m];
    g_xfret[(size_t)c * MTOT + m] = v;
}

// ---------------- mem transpose [64][256] -> [256][64] ----------------
__global__ void k_mem_t(const float* __restrict__ mem) {
    int id = blockIdx.x * 256 + threadIdx.x;   // 16384
    int j = id >> 8, n = id & 255;
    g_memT[n * MEMN + j] = mem[id];
}

// ---------------- logits + softmax (rows of 64), writes attnT [64][M] ----------------
__global__ void __launch_bounds__(256) k_logits_softmax(const float* __restrict__ keys) {
    __shared__ float qs[16][128];
    __shared__ float ks[16][64];
    __shared__ float red[128][8];
    __shared__ float rowred[128];
    int tid = threadIdx.x;
    int m0 = blockIdx.x * 128;
    float acc[4][8];
#pragma unroll
    for (int i = 0; i < 4; i++)
#pragma unroll
        for (int j = 0; j < 8; j++) acc[i][j] = 0.f;
    int m4 = tid & 31, kr = tid >> 5;
    int jb = tid & 63, kq = tid >> 6;
    int tx = tid & 7, ty = tid >> 3;
    for (int k0 = 0; k0 < 256; k0 += 16) {
#pragma unroll
        for (int s = 0; s < 2; s++) {
            int kk = kr + s * 8;
            *(float4*)&qs[kk][m4 * 4] =
                *(const float4*)&g_q[(size_t)(k0 + kk) * MTOT + m0 + m4 * 4];
        }
        {
            float4 v = *(const float4*)&keys[jb * 256 + k0 + kq * 4];
            ks[kq * 4 + 0][jb] = v.x; ks[kq * 4 + 1][jb] = v.y;
            ks[kq * 4 + 2][jb] = v.z; ks[kq * 4 + 3][jb] = v.w;
        }
        __syncthreads();
#pragma unroll
        for (int kk = 0; kk < 16; kk++) {
            float a[4], b[8];
#pragma unroll
            for (int i = 0; i < 4; i++) a[i] = qs[kk][ty * 4 + i];
#pragma unroll
            for (int j = 0; j < 8; j++) b[j] = ks[kk][tx * 8 + j];
#pragma unroll
            for (int i = 0; i < 4; i++)
#pragma unroll
                for (int j = 0; j < 8; j++) acc[i][j] = fmaf(a[i], b[j], acc[i][j]);
        }
        __syncthreads();
    }
    const float sc = 0.0625f;   // 1/sqrt(256)
#pragma unroll
    for (int i = 0; i < 4; i++) {
        float mx = -1e30f;
#pragma unroll
        for (int j = 0; j < 8; j++) { acc[i][j] *= sc; mx = fmaxf(mx, acc[i][j]); }
        red[ty * 4 + i][tx] = mx;
    }
    __syncthreads();
    if (tid < 128) {
        float mx = -1e30f;
        for (int t = 0; t < 8; t++) mx = fmaxf(mx, red[tid][t]);
        rowred[tid] = mx;
    }
    __syncthreads();
#pragma unroll
    for (int i = 0; i < 4; i++) {
        float rm = rowred[ty * 4 + i], s = 0.f;
#pragma unroll
        for (int j = 0; j < 8; j++) { acc[i][j] = expf(acc[i][j] - rm); s += acc[i][j]; }
        red[ty * 4 + i][tx] = s;
    }
    __syncthreads();
    if (tid < 128) {
        float s = 0.f;
        for (int t = 0; t < 8; t++) s += red[tid][t];
        rowred[tid] = 1.f / s;
    }
    __syncthreads();
#pragma unroll
    for (int i = 0; i < 4; i++) {
        float inv = rowred[ty * 4 + i];
#pragma unroll
        for (int j = 0; j < 8; j++)
            g_attn[(size_t)(tx * 8 + j) * MTOT + m0 + ty * 4 + i] = acc[i][j] * inv;
    }
}

// ---------------- final: spike + BN(shortcut) + relu, write NCHW ----------------
__global__ void k_final(float* __restrict__ out) {
    int c = blockIdx.y;
    int m = blockIdx.x * 256 + threadIdx.x;
    float mo = g_mo[(size_t)c * MTOT + m];
    float spike = (0.1f * mo >= 1.0f) ? 1.f : 0.f;
    float idv = fmaf(g_asc[c], g_id[(size_t)c * MTOT + m], g_csc[c]);
    int b = m >> 10, p = m & 1023;
    out[(size_t)b * CO * HWP + c * HWP + p] = fmaxf(spike + idv, 0.f);
}

// =============================== host launcher ===============================
extern "C" void kernel_launch(void* const* d_in, const int* in_sizes, int n_in,
                              void* d_out, int out_size) {
    const float* x       = (const float*)d_in[0];
    const float* conv1_w = (const float*)d_in[1];
    const float* conv1_b = (const float*)d_in[2];
    const float* bn1_g   = (const float*)d_in[3];
    const float* bn1_b   = (const float*)d_in[4];
    const float* conv2_w = (const float*)d_in[5];
    const float* conv2_b = (const float*)d_in[6];
    const float* bn2_g   = (const float*)d_in[7];
    const float* bn2_b   = (const float*)d_in[8];
    const float* ca_w1   = (const float*)d_in[9];
    const float* ca_w2   = (const float*)d_in[10];
    const float* sa_w    = (const float*)d_in[11];
    const float* sa_b    = (const float*)d_in[12];
    const float* memp    = (const float*)d_in[13];
    const float* mem_keys= (const float*)d_in[14];
    const float* ctrl_w1 = (const float*)d_in[15];
    const float* ctrl_b1 = (const float*)d_in[16];
    const float* ctrl_w2 = (const float*)d_in[17];
    const float* ctrl_b2 = (const float*)d_in[18];
    const float* gate_w  = (const float*)d_in[19];
    const float* gate_b  = (const float*)d_in[20];
    const float* sc_w    = (const float*)d_in[21];
    const float* sc_g    = (const float*)d_in[22];
    const float* sc_b    = (const float*)d_in[23];

    float *xT, *t1, *t2, *idb, *hb, *qb, *xfret, *attn, *mo, *memT;
    float *a1, *c1, *a2, *c2, *asc, *csc;
    cudaGetSymbolAddress((void**)&xT, g_xT);
    cudaGetSymbolAddress((void**)&t1, g_t1);
    cudaGetSymbolAddress((void**)&t2, g_t2);
    cudaGetSymbolAddress((void**)&idb, g_id);
    cudaGetSymbolAddress((void**)&hb, g_h);
    cudaGetSymbolAddress((void**)&qb, g_q);
    cudaGetSymbolAddress((void**)&xfret, g_xfret);
    cudaGetSymbolAddress((void**)&attn, g_attn);
    cudaGetSymbolAddress((void**)&mo, g_mo);
    cudaGetSymbolAddress((void**)&memT, g_memT);
    cudaGetSymbolAddress((void**)&a1, g_a1);
    cudaGetSymbolAddress((void**)&c1, g_c1);
    cudaGetSymbolAddress((void**)&a2, g_a2);
    cudaGetSymbolAddress((void**)&c2, g_c2);
    cudaGetSymbolAddress((void**)&asc, g_asc);
    cudaGetSymbolAddress((void**)&csc, g_csc);

    dim3 gemm_grid(MTOT / 128, 2);   // N = 256 always

    // 1) transpose input
    k_transpose_x<<<BB * CINN * HWP / 256, 256>>>(x);

    // 2) shortcut conv (1x1): plain GEMM K=128
    k_gemm_tc<0><<<gemm_grid, 256>>>(xT, sc_w, nullptr, idb, 128, nullptr, nullptr);
    k_reduce_coeffs<0><<<CO, 256>>>(idb, sc_g, sc_b, asc, csc);

    // 3) conv1: implicit-GEMM (K=1152) straight from xT
    k_conv_tc<0><<<gemm_grid, 256>>>(xT, conv1_w, conv1_b, t1, CINN * 9,
                                     nullptr, nullptr);
    k_reduce_coeffs<0><<<CO, 256>>>(t1, bn1_g, bn1_b, a1, c1);

    // 4) conv2: implicit-GEMM (K=2304) with fused BN1+ReLU in the gather
    k_conv_tc<1><<<gemm_grid, 256>>>(t1, conv2_w, conv2_b, t2, CO * 9, a1, c1);
    k_reduce_coeffs<1><<<CO, 256>>>(t2, bn2_g, bn2_b, a2, c2);

    // 5) channel attention (uses per-(b,c) stats of t2)
    k_ca_mlp<<<BB, 256>>>(ca_w1, ca_w2);

    // 6) spatial attention
    k_sp_pool<<<MTOT / 256, 256>>>();
    k_sa_conv<<<BB, 1024>>>(sa_w, sa_b);

    // 7) xf (attention-applied features) into front half of xfret buffer
    k_build_xf<<<dim3(MTOT / 256, CO), 256>>>();

    // 8) memory module
    k_gemm_tc<1><<<gemm_grid, 256>>>(xfret, ctrl_w1, ctrl_b1, hb, 256, nullptr, nullptr);
    k_gemm_tc<0><<<gemm_grid, 256>>>(hb, ctrl_w2, ctrl_b2, qb, 256, nullptr, nullptr);
    k_mem_t<<<MEMN * CO / 256, 256>>>(memp);
    k_logits_softmax<<<MTOT / 128, 256>>>(mem_keys);
    k_gemm_tc<0><<<gemm_grid, 256>>>(attn, memT, nullptr, xfret + (size_t)256 * MTOT,
                                     MEMN, nullptr, nullptr);
    k_gemm_tc<2><<<gemm_grid, 256>>>(xfret, gate_w, gate_b, mo, 512,
                                     xfret, xfret + (size_t)256 * MTOT);

    // 9) spike + shortcut + relu -> NCHW output
    k_final<<<dim3(MTOT / 256, CO), 256>>>((float*)d_out);
}

// round 14
// speedup vs baseline: 2.7221x; 1.3173x over previous
#include <cuda_runtime.h>
#include <cuda_bf16.h>
#include <math.h>
#include <stdint.h>

#define CDIV(a,b) (((a)+(b)-1)/(b))

static constexpr int BB   = 32;
static constexpr int CINN = 128;
static constexpr int CO   = 256;
static constexpr int HWP  = 1024;          // 32*32
static constexpr int MTOT = BB * HWP;      // 32768
static constexpr int MEMN = 64;

// ---------------- scratch (static device memory; no allocations) ----------------
__device__ float g_xT   [(size_t)CINN * MTOT];        // x transposed  [128][M]
__device__ float g_t1   [(size_t)CO * MTOT];          // conv1 raw     [256][M]
__device__ float g_t2   [(size_t)CO * MTOT];          // conv2 raw
__device__ float g_id   [(size_t)CO * MTOT];          // shortcut conv raw
__device__ float g_h    [(size_t)CO * MTOT];          // ctrl hidden
__device__ float g_q    [(size_t)CO * MTOT];          // ctrl out (query)
__device__ float g_xfret[(size_t)512 * MTOT];         // [xfT(256) ; retT(256)][M]
__device__ float g_attn [(size_t)MEMN * MTOT];        // attn transposed [64][M]
__device__ float g_mo   [(size_t)CO * MTOT];          // memory out
__device__ float g_memT [CO * MEMN];                  // mem transposed [256][64]
__device__ float4 g_stats2 [CO * BB];                 // conv2 per-(c,b) stats (for CA)
__device__ float g_a1[CO], g_c1[CO], g_a2[CO], g_c2[CO], g_asc[CO], g_csc[CO];
__device__ float g_chatt[BB * CO];
__device__ float g_spmean[MTOT], g_spmax[MTOT], g_sa[MTOT];

// ---------------- bf16 hi/lo helpers ----------------
__device__ __forceinline__ void cvt_hilo_bf16(float x, uint16_t& h, uint16_t& l) {
    __nv_bfloat16 hb = __float2bfloat16_rn(x);
    float r = x - __bfloat162float(hb);
    __nv_bfloat16 lb = __float2bfloat16_rn(r);
    h = __bfloat16_as_ushort(hb);
    l = __bfloat16_as_ushort(lb);
}
__device__ __forceinline__ uint32_t pack2(uint16_t e, uint16_t o) {
    return (uint32_t)e | ((uint32_t)o << 16);      // low bits = even(k), high = odd(k+1)
}

#define MMA_BF16(Cv, Af, Bf)                                                     \
    asm volatile("mma.sync.aligned.m16n8k16.row.col.f32.bf16.bf16.f32 "          \
                 "{%0,%1,%2,%3},{%4,%5,%6,%7},{%8,%9},{%0,%1,%2,%3};"            \
                 : "+f"(Cv[0]), "+f"(Cv[1]), "+f"(Cv[2]), "+f"(Cv[3])            \
                 : "r"(Af[0]), "r"(Af[1]), "r"(Af[2]), "r"(Af[3]),               \
                   "r"(Bf[0]), "r"(Bf[1]));

// ---------------- transpose x: NCHW -> [ci][b*1024+p] ----------------
__global__ void k_transpose_x(const float* __restrict__ x) {
    int id = blockIdx.x * 256 + threadIdx.x;      // 32*128*1024 total
    float v = x[id];
    int p  = id & 1023;
    int ci = (id >> 10) & 127;
    int b  = id >> 17;
    g_xT[(size_t)ci * MTOT + b * HWP + p] = v;
}

static constexpr int SMS = 136;   // padded smem row stride (conflict-free frag loads)

// ======================= shared GEMM core (bf16x3 mma) =======================
// Block tile 128(m) x 128(n) x 16(k). 8 warps: 2(m) x 4(n); warp tile 64x32.
// Smem rows = k-PAIRS (8 rows per 16-k tile), elements = packed bf16x2.

__device__ __forceinline__ void mma_block(
    uint32_t (&Ah)[8][SMS], uint32_t (&Al)[8][SMS],
    uint32_t (&Bh)[8][SMS], uint32_t (&Bl)[8][SMS],
    int wm, int wn, int gid, int tig, float (&c)[4][4][4]) {
    uint32_t bfh[4][2], bfl[4][2];
#pragma unroll
    for (int j = 0; j < 4; j++) {
        int nc = wn + j * 8 + gid;
        bfh[j][0] = Bh[tig][nc];
        bfh[j][1] = Bh[tig + 4][nc];
        bfl[j][0] = Bl[tig][nc];
        bfl[j][1] = Bl[tig + 4][nc];
    }
#pragma unroll
    for (int i = 0; i < 4; i++) {
        int mr = wm + i * 16;
        uint32_t afh[4], afl[4];
        afh[0] = Ah[tig][mr + gid];
        afh[1] = Ah[tig][mr + gid + 8];
        afh[2] = Ah[tig + 4][mr + gid];
        afh[3] = Ah[tig + 4][mr + gid + 8];
        afl[0] = Al[tig][mr + gid];
        afl[1] = Al[tig][mr + gid + 8];
        afl[2] = Al[tig + 4][mr + gid];
        afl[3] = Al[tig + 4][mr + gid + 8];
#pragma unroll
        for (int j = 0; j < 4; j++) {
            MMA_BF16(c[i][j], afh, bfh[j]);
            MMA_BF16(c[i][j], afh, bfl[j]);
            MMA_BF16(c[i][j], afl, bfh[j]);
        }
    }
}

// store A pair-rows: ve = values at even k (4 consecutive m), vo = odd k
__device__ __forceinline__ void stA_pair(uint32_t (&Ah)[8][SMS], uint32_t (&Al)[8][SMS],
                                         int kp, int am, float4 ve, float4 vo) {
    uint16_t he[4], le[4], ho[4], lo_[4];
    cvt_hilo_bf16(ve.x, he[0], le[0]); cvt_hilo_bf16(ve.y, he[1], le[1]);
    cvt_hilo_bf16(ve.z, he[2], le[2]); cvt_hilo_bf16(ve.w, he[3], le[3]);
    cvt_hilo_bf16(vo.x, ho[0], lo_[0]); cvt_hilo_bf16(vo.y, ho[1], lo_[1]);
    cvt_hilo_bf16(vo.z, ho[2], lo_[2]); cvt_hilo_bf16(vo.w, ho[3], lo_[3]);
    uint4 H = make_uint4(pack2(he[0], ho[0]), pack2(he[1], ho[1]),
                         pack2(he[2], ho[2]), pack2(he[3], ho[3]));
    uint4 L = make_uint4(pack2(le[0], lo_[0]), pack2(le[1], lo_[1]),
                         pack2(le[2], lo_[2]), pack2(le[3], lo_[3]));
    *(uint4*)&Ah[kp][am] = H;
    *(uint4*)&Al[kp][am] = L;
}

// store B: v = 4 consecutive k at fixed n -> pair rows p, p+1
__device__ __forceinline__ void stB_pair(uint32_t (&Bh)[8][SMS], uint32_t (&Bl)[8][SMS],
                                         int p, int bn, float4 v) {
    uint16_t h0, l0, h1, l1, h2, l2, h3, l3;
    cvt_hilo_bf16(v.x, h0, l0); cvt_hilo_bf16(v.y, h1, l1);
    cvt_hilo_bf16(v.z, h2, l2); cvt_hilo_bf16(v.w, h3, l3);
    Bh[p][bn]     = pack2(h0, h1); Bl[p][bn]     = pack2(l0, l1);
    Bh[p + 1][bn] = pack2(h2, h3); Bl[p + 1][bn] = pack2(l2, l3);
}

// ---------------- tensor-core GEMM (3xBF16): C[n][m] = sum_k A[k][m]*B[n][k] ------
// EPI: 0 = bias, 1 = bias+relu, 2 = gate epilogue (sigmoid(acc+bias); blend ret/xf)
template <int EPI>
__global__ void __launch_bounds__(256, 2)
k_gemm_tc(const float* __restrict__ A, const float* __restrict__ Bw,
          const float* __restrict__ bias, float* __restrict__ C, int K,
          const float* __restrict__ e_xf, const float* __restrict__ e_ret) {
    __shared__ uint32_t Ah[8][SMS], Al[8][SMS], Bh[8][SMS], Bl[8][SMS];
    int tid = threadIdx.x;
    int m0 = blockIdx.x * 128, n0 = blockIdx.y * 128;
    int wid = tid >> 5, lane = tid & 31;
    int wm = (wid & 1) * 64;
    int wn = (wid >> 1) * 32;
    int gid = lane >> 2, tig = lane & 3;

    float c[4][4][4];
#pragma unroll
    for (int i = 0; i < 4; i++)
#pragma unroll
        for (int j = 0; j < 4; j++)
#pragma unroll
            for (int r = 0; r < 4; r++) c[i][j][r] = 0.f;

    int am = (tid & 31) * 4, kp = tid >> 5;    // A loader: k-pair row kp (0..7)
    int bn = tid & 127, bk4 = (tid >> 7) * 4;  // B loader

    float4 rA[2], rB[2];
#pragma unroll
    for (int s = 0; s < 2; s++)
        rA[s] = *(const float4*)&A[(size_t)(2 * kp + s) * MTOT + m0 + am];
#pragma unroll
    for (int s = 0; s < 2; s++)
        rB[s] = *(const float4*)&Bw[(size_t)(n0 + bn) * K + bk4 + s * 8];

    for (int k0 = 0; k0 < K; k0 += 16) {
        stA_pair(Ah, Al, kp, am, rA[0], rA[1]);
#pragma unroll
        for (int s = 0; s < 2; s++)
            stB_pair(Bh, Bl, (bk4 + s * 8) >> 1, bn, rB[s]);
        __syncthreads();
        int kn = k0 + 16;
        if (kn < K) {
#pragma unroll
            for (int s = 0; s < 2; s++)
                rA[s] = *(const float4*)&A[(size_t)(kn + 2 * kp + s) * MTOT + m0 + am];
#pragma unroll
            for (int s = 0; s < 2; s++)
                rB[s] = *(const float4*)&Bw[(size_t)(n0 + bn) * K + kn + bk4 + s * 8];
        }
        mma_block(Ah, Al, Bh, Bl, wm, wn, gid, tig, c);
        __syncthreads();
    }

#pragma unroll
    for (int i = 0; i < 4; i++) {
        int mlo = m0 + wm + i * 16 + gid;
#pragma unroll
        for (int j = 0; j < 4; j++) {
            int nlo = n0 + wn + j * 8 + 2 * tig;
            float b0 = bias ? bias[nlo] : 0.f;
            float b1 = bias ? bias[nlo + 1] : 0.f;
#pragma unroll
            for (int r = 0; r < 4; r++) {
                int n = nlo + (r & 1);
                int m = mlo + (r >> 1) * 8;
                float v = c[i][j][r] + ((r & 1) ? b1 : b0);
                if (EPI == 1) v = fmaxf(v, 0.f);
                if (EPI == 2) {
                    float g = 1.f / (1.f + expf(-v));
                    size_t off = (size_t)n * MTOT + m;
                    v = g * e_ret[off] + (1.f - g) * e_xf[off];
                }
                C[(size_t)n * MTOT + m] = v;
            }
        }
    }
}

// ---------------- implicit-GEMM conv (3x3, pad 1) on tensor cores ----------------
// A[k][m] gathered on the fly from src[ci][b*1024 + (h+dh)*32 + (w+dw)] with
// zero padding; k = ci*9 + (dh+1)*3 + (dw+1). ACT=1: fuse BN+ReLU of src.
template <int ACT>
__global__ void __launch_bounds__(256, 2)
k_conv_tc(const float* __restrict__ src, const float* __restrict__ Bw,
          const float* __restrict__ bias, float* __restrict__ C, int K,
          const float* __restrict__ aa, const float* __restrict__ cc) {
    __shared__ uint32_t Ah[8][SMS], Al[8][SMS], Bh[8][SMS], Bl[8][SMS];
    int tid = threadIdx.x;
    int m0 = blockIdx.x * 128, n0 = blockIdx.y * 128;
    int wid = tid >> 5, lane = tid & 31;
    int wm = (wid & 1) * 64;
    int wn = (wid >> 1) * 32;
    int gid = lane >> 2, tig = lane & 3;

    float c[4][4][4];
#pragma unroll
    for (int i = 0; i < 4; i++)
#pragma unroll
        for (int j = 0; j < 4; j++)
#pragma unroll
            for (int r = 0; r < 4; r++) c[i][j][r] = 0.f;

    int am = (tid & 31) * 4, kp = tid >> 5;    // A loader: k-pair (2kp, 2kp+1)
    int bn = tid & 127, bk4 = (tid >> 7) * 4;  // B loader

    int pm = (m0 + am) & 1023;                 // batch-invariant image position
    int hbase = pm >> 5, wbase = pm & 31;

    auto gatherA = [&](int k, float (&v)[4], int& ci_out) {
        int ci = k / 9, r = k - ci * 9;
        int dh = r / 3 - 1, dw = r - (r / 3) * 3 - 1;
        int h  = hbase + dh;
        bool hok = (unsigned)h < 32u;
        const float* sp = src + (size_t)ci * MTOT + (m0 + am) + dh * 32 + dw;
#pragma unroll
        for (int e = 0; e < 4; e++) {
            int w = wbase + dw + e;
            v[e] = (hok && (unsigned)w < 32u) ? __ldg(sp + e) : 0.f;
        }
        ci_out = ci;
    };

    float vA[2][4]; int ciA[2];
    float4 rB[2];
#pragma unroll
    for (int s = 0; s < 2; s++) {
        gatherA(2 * kp + s, vA[s], ciA[s]);
        rB[s] = *(const float4*)&Bw[(size_t)(n0 + bn) * K + bk4 + s * 8];
    }

    for (int k0 = 0; k0 < K; k0 += 16) {
        float4 rows[2];
#pragma unroll
        for (int s = 0; s < 2; s++) {
            float v0 = vA[s][0], v1 = vA[s][1], v2 = vA[s][2], v3 = vA[s][3];
            if (ACT) {
                float a = aa[ciA[s]], cbv = cc[ciA[s]];
                v0 = fmaxf(fmaf(a, v0, cbv), 0.f);
                v1 = fmaxf(fmaf(a, v1, cbv), 0.f);
                v2 = fmaxf(fmaf(a, v2, cbv), 0.f);
                v3 = fmaxf(fmaf(a, v3, cbv), 0.f);
            }
            rows[s] = make_float4(v0, v1, v2, v3);
        }
        stA_pair(Ah, Al, kp, am, rows[0], rows[1]);
#pragma unroll
        for (int s = 0; s < 2; s++)
            stB_pair(Bh, Bl, (bk4 + s * 8) >> 1, bn, rB[s]);
        __syncthreads();
        int kn = k0 + 16;
        if (kn < K) {
#pragma unroll
            for (int s = 0; s < 2; s++) {
                gatherA(kn + 2 * kp + s, vA[s], ciA[s]);
                rB[s] = *(const float4*)&Bw[(size_t)(n0 + bn) * K + kn + bk4 + s * 8];
            }
        }
        mma_block(Ah, Al, Bh, Bl, wm, wn, gid, tig, c);
        __syncthreads();
    }

#pragma unroll
    for (int i = 0; i < 4; i++) {
        int mlo = m0 + wm + i * 16 + gid;
#pragma unroll
        for (int j = 0; j < 4; j++) {
            int nlo = n0 + wn + j * 8 + 2 * tig;
            float b0 = bias[nlo], b1 = bias[nlo + 1];
#pragma unroll
            for (int r = 0; r < 4; r++) {
                int n = nlo + (r & 1);
                int m = mlo + (r >> 1) * 8;
                C[(size_t)n * MTOT + m] = c[i][j][r] + ((r & 1) ? b1 : b0);
            }
        }
    }
}

// ------- fused per-channel reduction + BN coeffs (one block per channel) -------
template <int STORE_STATS>
__global__ void __launch_bounds__(256) k_reduce_coeffs(
    const float* __restrict__ src, const float* __restrict__ g,
    const float* __restrict__ beta, float* __restrict__ a, float* __restrict__ cc) {
    int ch = blockIdx.x;
    int tid = threadIdx.x;
    int lane = tid & 31, wrp = tid >> 5;
    __shared__ float4 wred[8];
    __shared__ float tot[2];
    if (tid == 0) { tot[0] = 0.f; tot[1] = 0.f; }
    for (int b = 0; b < BB; b++) {
        const float* p = src + (size_t)(ch * BB + b) * HWP;
        float v0 = p[tid], v1 = p[tid + 256], v2 = p[tid + 512], v3 = p[tid + 768];
        float s  = v0 + v1 + v2 + v3;
        float ss = v0 * v0 + v1 * v1 + v2 * v2 + v3 * v3;
        float mx = fmaxf(fmaxf(v0, v1), fmaxf(v2, v3));
        float mn = fminf(fminf(v0, v1), fminf(v2, v3));
#pragma unroll
        for (int o = 16; o; o >>= 1) {
            s  += __shfl_down_sync(0xffffffffu, s, o);
            ss += __shfl_down_sync(0xffffffffu, ss, o);
            mx = fmaxf(mx, __shfl_down_sync(0xffffffffu, mx, o));
            mn = fminf(mn, __shfl_down_sync(0xffffffffu, mn, o));
        }
        if (lane == 0) wred[wrp] = make_float4(s, ss, mx, mn);
        __syncthreads();
        if (tid == 0) {
            float4 r = wred[0];
            for (int i = 1; i < 8; i++) {
                r.x += wred[i].x; r.y += wred[i].y;
                r.z = fmaxf(r.z, wred[i].z); r.w = fminf(r.w, wred[i].w);
            }
            if (STORE_STATS) g_stats2[ch * BB + b] = r;
            tot[0] += r.x; tot[1] += r.y;
        }
        __syncthreads();
    }
    if (tid == 0) {
        float mean = tot[0] * (1.f / 32768.f);
        float var  = tot[1] * (1.f / 32768.f) - mean * mean;
        float av = g[ch] * rsqrtf(var + 1e-5f);
        a[ch] = av;
        cc[ch] = beta[ch] - av * mean;
    }
}

// ---------------- channel attention MLP ----------------
__global__ void __launch_bounds__(256) k_ca_mlp(const float* __restrict__ w1,
                                                const float* __restrict__ w2) {
    int b = blockIdx.x, tid = threadIdx.x;
    __shared__ float va[CO], vm[CO], hsum[16];
    {
        float4 st = g_stats2[tid * BB + b];
        float a = g_a2[tid], c = g_c2[tid];
        va[tid] = a * st.x * (1.f / 1024.f) + c;
        vm[tid] = (a >= 0.f ? a * st.z : a * st.w) + c;
    }
    __syncthreads();
    int wid = tid >> 5, lane = tid & 31;
    for (int u = 0; u < 2; u++) {
        int j = wid * 2 + u;
        float sa = 0.f, sm = 0.f;
        for (int c = lane; c < CO; c += 32) {
            float wv = w1[j * CO + c];
            sa += wv * va[c]; sm += wv * vm[c];
        }
#pragma unroll
        for (int o = 16; o; o >>= 1) {
            sa += __shfl_down_sync(0xffffffffu, sa, o);
            sm += __shfl_down_sync(0xffffffffu, sm, o);
        }
        if (lane == 0) hsum[j] = fmaxf(sa, 0.f) + fmaxf(sm, 0.f);
    }
    __syncthreads();
    float s = 0.f;
    for (int j = 0; j < 16; j++) s += hsum[j] * w2[tid * 16 + j];
    g_chatt[b * CO + tid] = 1.f / (1.f + expf(-s));
}

// ---------------- spatial pooling over channels (mean & max) ----------------
__global__ void __launch_bounds__(256) k_sp_pool() {
    int m = blockIdx.x * 256 + threadIdx.x;
    int b = m >> 10;
    __shared__ float co[CO], of[CO];
    {
        int t = threadIdx.x;
        float ca = g_chatt[b * CO + t];
        co[t] = ca * g_a2[t];
        of[t] = ca * g_c2[t];
    }
    __syncthreads();
    float s = 0.f, mx = -1e30f;
    for (int c = 0; c < CO; c++) {
        float v = fmaf(co[c], g_t2[(size_t)c * MTOT + m], of[c]);
        s += v; mx = fmaxf(mx, v);
    }
    g_spmean[m] = s * (1.f / 256.f);
    g_spmax[m]  = mx;
}

// ---------------- spatial attention 7x7 conv + sigmoid ----------------
__global__ void __launch_bounds__(1024) k_sa_conv(const float* __restrict__ sw,
                                                  const float* __restrict__ sb) {
    int b = blockIdx.x, p = threadIdx.x;
    __shared__ float me[HWP], ma[HWP];
    me[p] = g_spmean[b * HWP + p];
    ma[p] = g_spmax[b * HWP + p];
    __syncthreads();
    int h = p >> 5, w = p & 31;
    float acc = sb[0];
#pragma unroll
    for (int kh = 0; kh < 7; kh++) {
        int hh = h + kh - 3;
        if ((unsigned)hh >= 32u) continue;
#pragma unroll
        for (int kw = 0; kw < 7; kw++) {
            int ww = w + kw - 3;
            if ((unsigned)ww >= 32u) continue;
            int q = hh * 32 + ww;
            acc += sw[kh * 7 + kw] * me[q] + sw[49 + kh * 7 + kw] * ma[q];
        }
    }
    g_sa[b * HWP + p] = 1.f / (1.f + expf(-acc));
}

// ---------------- build xf (post channel+spatial attention), T layout ----------------
__global__ void k_build_xf() {
    int c = blockIdx.y;
    int m = blockIdx.x * 256 + threadIdx.x;
    int b = m >> 10;
    float ca = g_chatt[b * CO + c];
    float v = ca * fmaf(g_a2[c], g_t2[(size_t)c * MTOT + m], g_c2[c]) * g_sa[m];
    g_xfret[(size_t)c * MTOT + m] = v;
}

// ---------------- mem transpose [64][256] -> [256][64] ----------------
__global__ void k_mem_t(const float* __restrict__ mem) {
    int id = blockIdx.x * 256 + threadIdx.x;   // 16384
    int j = id >> 8, n = id & 255;
    g_memT[n * MEMN + j] = mem[id];
}

// ---------------- logits + softmax (rows of 64), writes attnT [64][M] ----------------
__global__ void __launch_bounds__(256) k_logits_softmax(const float* __restrict__ keys) {
    __shared__ float qs[16][128];
    __shared__ float ks[16][64];
    __shared__ float red[128][8];
    __shared__ float rowred[128];
    int tid = threadIdx.x;
    int m0 = blockIdx.x * 128;
    float acc[4][8];
#pragma unroll
    for (int i = 0; i < 4; i++)
#pragma unroll
        for (int j = 0; j < 8; j++) acc[i][j] = 0.f;
    int m4 = tid & 31, kr = tid >> 5;
    int jb = tid & 63, kq = tid >> 6;
    int tx = tid & 7, ty = tid >> 3;
    for (int k0 = 0; k0 < 256; k0 += 16) {
#pragma unroll
        for (int s = 0; s < 2; s++) {
            int kk = kr + s * 8;
            *(float4*)&qs[kk][m4 * 4] =
                *(const float4*)&g_q[(size_t)(k0 + kk) * MTOT + m0 + m4 * 4];
        }
        {
            float4 v = *(const float4*)&keys[jb * 256 + k0 + kq * 4];
            ks[kq * 4 + 0][jb] = v.x; ks[kq * 4 + 1][jb] = v.y;
            ks[kq * 4 + 2][jb] = v.z; ks[kq * 4 + 3][jb] = v.w;
        }
        __syncthreads();
#pragma unroll
        for (int kk = 0; kk < 16; kk++) {
            float a[4], b[8];
#pragma unroll
            for (int i = 0; i < 4; i++) a[i] = qs[kk][ty * 4 + i];
#pragma unroll
            for (int j = 0; j < 8; j++) b[j] = ks[kk][tx * 8 + j];
#pragma unroll
            for (int i = 0; i < 4; i++)
#pragma unroll
                for (int j = 0; j < 8; j++) acc[i][j] = fmaf(a[i], b[j], acc[i][j]);
        }
        __syncthreads();
    }
    const float sc = 0.0625f;   // 1/sqrt(256)
#pragma unroll
    for (int i = 0; i < 4; i++) {
        float mx = -1e30f;
#pragma unroll
        for (int j = 0; j < 8; j++) { acc[i][j] *= sc; mx = fmaxf(mx, acc[i][j]); }
        red[ty * 4 + i][tx] = mx;
    }
    __syncthreads();
    if (tid < 128) {
        float mx = -1e30f;
        for (int t = 0; t < 8; t++) mx = fmaxf(mx, red[tid][t]);
        rowred[tid] = mx;
    }
    __syncthreads();
#pragma unroll
    for (int i = 0; i < 4; i++) {
        float rm = rowred[ty * 4 + i], s = 0.f;
#pragma unroll
        for (int j = 0; j < 8; j++) { acc[i][j] = expf(acc[i][j] - rm); s += acc[i][j]; }
        red[ty * 4 + i][tx] = s;
    }
    __syncthreads();
    if (tid < 128) {
        float s = 0.f;
        for (int t = 0; t < 8; t++) s += red[tid][t];
        rowred[tid] = 1.f / s;
    }
    __syncthreads();
#pragma unroll
    for (int i = 0; i < 4; i++) {
        float inv = rowred[ty * 4 + i];
#pragma unroll
        for (int j = 0; j < 8; j++)
            g_attn[(size_t)(tx * 8 + j) * MTOT + m0 + ty * 4 + i] = acc[i][j] * inv;
    }
}

// ---------------- final: spike + BN(shortcut) + relu, write NCHW ----------------
__global__ void k_final(float* __restrict__ out) {
    int c = blockIdx.y;
    int m = blockIdx.x * 256 + threadIdx.x;
    float mo = g_mo[(size_t)c * MTOT + m];
    float spike = (0.1f * mo >= 1.0f) ? 1.f : 0.f;
    float idv = fmaf(g_asc[c], g_id[(size_t)c * MTOT + m], g_csc[c]);
    int b = m >> 10, p = m & 1023;
    out[(size_t)b * CO * HWP + c * HWP + p] = fmaxf(spike + idv, 0.f);
}

// =============================== host launcher ===============================
extern "C" void kernel_launch(void* const* d_in, const int* in_sizes, int n_in,
                              void* d_out, int out_size) {
    const float* x       = (const float*)d_in[0];
    const float* conv1_w = (const float*)d_in[1];
    const float* conv1_b = (const float*)d_in[2];
    const float* bn1_g   = (const float*)d_in[3];
    const float* bn1_b   = (const float*)d_in[4];
    const float* conv2_w = (const float*)d_in[5];
    const float* conv2_b = (const float*)d_in[6];
    const float* bn2_g   = (const float*)d_in[7];
    const float* bn2_b   = (const float*)d_in[8];
    const float* ca_w1   = (const float*)d_in[9];
    const float* ca_w2   = (const float*)d_in[10];
    const float* sa_w    = (const float*)d_in[11];
    const float* sa_b    = (const float*)d_in[12];
    const float* memp    = (const float*)d_in[13];
    const float* mem_keys= (const float*)d_in[14];
    const float* ctrl_w1 = (const float*)d_in[15];
    const float* ctrl_b1 = (const float*)d_in[16];
    const float* ctrl_w2 = (const float*)d_in[17];
    const float* ctrl_b2 = (const float*)d_in[18];
    const float* gate_w  = (const float*)d_in[19];
    const float* gate_b  = (const float*)d_in[20];
    const float* sc_w    = (const float*)d_in[21];
    const float* sc_g    = (const float*)d_in[22];
    const float* sc_b    = (const float*)d_in[23];

    float *xT, *t1, *t2, *idb, *hb, *qb, *xfret, *attn, *mo, *memT;
    float *a1, *c1, *a2, *c2, *asc, *csc;
    cudaGetSymbolAddress((void**)&xT, g_xT);
    cudaGetSymbolAddress((void**)&t1, g_t1);
    cudaGetSymbolAddress((void**)&t2, g_t2);
    cudaGetSymbolAddress((void**)&idb, g_id);
    cudaGetSymbolAddress((void**)&hb, g_h);
    cudaGetSymbolAddress((void**)&qb, g_q);
    cudaGetSymbolAddress((void**)&xfret, g_xfret);
    cudaGetSymbolAddress((void**)&attn, g_attn);
    cudaGetSymbolAddress((void**)&mo, g_mo);
    cudaGetSymbolAddress((void**)&memT, g_memT);
    cudaGetSymbolAddress((void**)&a1, g_a1);
    cudaGetSymbolAddress((void**)&c1, g_c1);
    cudaGetSymbolAddress((void**)&a2, g_a2);
    cudaGetSymbolAddress((void**)&c2, g_c2);
    cudaGetSymbolAddress((void**)&asc, g_asc);
    cudaGetSymbolAddress((void**)&csc, g_csc);

    dim3 gemm_grid(MTOT / 128, 2);   // N = 256 always

    // 1) transpose input
    k_transpose_x<<<BB * CINN * HWP / 256, 256>>>(x);

    // 2) shortcut conv (1x1): plain GEMM K=128
    k_gemm_tc<0><<<gemm_grid, 256>>>(xT, sc_w, nullptr, idb, 128, nullptr, nullptr);
    k_reduce_coeffs<0><<<CO, 256>>>(idb, sc_g, sc_b, asc, csc);

    // 3) conv1: implicit-GEMM (K=1152) straight from xT
    k_conv_tc<0><<<gemm_grid, 256>>>(xT, conv1_w, conv1_b, t1, CINN * 9,
                                     nullptr, nullptr);
    k_reduce_coeffs<0><<<CO, 256>>>(t1, bn1_g, bn1_b, a1, c1);

    // 4) conv2: implicit-GEMM (K=2304) with fused BN1+ReLU in the gather
    k_conv_tc<1><<<gemm_grid, 256>>>(t1, conv2_w, conv2_b, t2, CO * 9, a1, c1);
    k_reduce_coeffs<1><<<CO, 256>>>(t2, bn2_g, bn2_b, a2, c2);

    // 5) channel attention (uses per-(b,c) stats of t2)
    k_ca_mlp<<<BB, 256>>>(ca_w1, ca_w2);

    // 6) spatial attention
    k_sp_pool<<<MTOT / 256, 256>>>();
    k_sa_conv<<<BB, 1024>>>(sa_w, sa_b);

    // 7) xf (attention-applied features) into front half of xfret buffer
    k_build_xf<<<dim3(MTOT / 256, CO), 256>>>();

    // 8) memory module
    k_gemm_tc<1><<<gemm_grid, 256>>>(xfret, ctrl_w1, ctrl_b1, hb, 256, nullptr, nullptr);
    k_gemm_tc<0><<<gemm_grid, 256>>>(hb, ctrl_w2, ctrl_b2, qb, 256, nullptr, nullptr);
    k_mem_t<<<MEMN * CO / 256, 256>>>(memp);
    k_logits_softmax<<<MTOT / 128, 256>>>(mem_keys);
    k_gemm_tc<0><<<gemm_grid, 256>>>(attn, memT, nullptr, xfret + (size_t)256 * MTOT,
                                     MEMN, nullptr, nullptr);
    k_gemm_tc<2><<<gemm_grid, 256>>>(xfret, gate_w, gate_b, mo, 512,
                                     xfret, xfret + (size_t)256 * MTOT);

    // 9) spike + shortcut + relu -> NCHW output
    k_final<<<dim3(MTOT / 256, CO), 256>>>((float*)d_out);
}

// round 15
// speedup vs baseline: 2.7228x; 1.0003x over previous
#include <cuda_runtime.h>
#include <cuda_bf16.h>
#include <math.h>
#include <stdint.h>

#define CDIV(a,b) (((a)+(b)-1)/(b))

static constexpr int BB   = 32;
static constexpr int CINN = 128;
static constexpr int CO   = 256;
static constexpr int HWP  = 1024;          // 32*32
static constexpr int MTOT = BB * HWP;      // 32768
static constexpr int MEMN = 64;

// ---------------- scratch (static device memory; no allocations) ----------------
__device__ float g_xT   [(size_t)CINN * MTOT];        // x transposed  [128][M]
__device__ float g_t1   [(size_t)CO * MTOT];          // conv1 raw     [256][M]
__device__ float g_t2   [(size_t)CO * MTOT];          // conv2 raw
__device__ float g_id   [(size_t)CO * MTOT];          // shortcut conv raw
__device__ float g_h    [(size_t)CO * MTOT];          // ctrl hidden
__device__ float g_q    [(size_t)CO * MTOT];          // ctrl out (query)
__device__ float g_xfret[(size_t)512 * MTOT];         // [xfT(256) ; retT(256)][M]
__device__ float g_attn [(size_t)MEMN * MTOT];        // attn transposed [64][M]
__device__ float g_mo   [(size_t)CO * MTOT];          // memory out
__device__ float g_memT [CO * MEMN];                  // mem transposed [256][64]
__device__ float4 g_stats2 [CO * BB];                 // conv2 per-(c,b) stats (for CA)
__device__ float g_a1[CO], g_c1[CO], g_a2[CO], g_c2[CO], g_asc[CO], g_csc[CO];
__device__ float g_chatt[BB * CO];
__device__ float g_spmean[MTOT], g_spmax[MTOT], g_sa[MTOT];

// ---------------- bf16 hi/lo helpers ----------------
__device__ __forceinline__ void cvt_hilo_bf16(float x, uint16_t& h, uint16_t& l) {
    __nv_bfloat16 hb = __float2bfloat16_rn(x);
    float r = x - __bfloat162float(hb);
    __nv_bfloat16 lb = __float2bfloat16_rn(r);
    h = __bfloat16_as_ushort(hb);
    l = __bfloat16_as_ushort(lb);
}
__device__ __forceinline__ uint32_t pack2(uint16_t e, uint16_t o) {
    return (uint32_t)e | ((uint32_t)o << 16);      // low bits = even(k), high = odd(k+1)
}

#define MMA_BF16(Cv, Af, Bf)                                                     \
    asm volatile("mma.sync.aligned.m16n8k16.row.col.f32.bf16.bf16.f32 "          \
                 "{%0,%1,%2,%3},{%4,%5,%6,%7},{%8,%9},{%0,%1,%2,%3};"            \
                 : "+f"(Cv[0]), "+f"(Cv[1]), "+f"(Cv[2]), "+f"(Cv[3])            \
                 : "r"(Af[0]), "r"(Af[1]), "r"(Af[2]), "r"(Af[3]),               \
                   "r"(Bf[0]), "r"(Bf[1]));

// ---------------- transpose x: NCHW -> [ci][b*1024+p] ----------------
__global__ void k_transpose_x(const float* __restrict__ x) {
    int id = blockIdx.x * 256 + threadIdx.x;      // 32*128*1024 total
    float v = x[id];
    int p  = id & 1023;
    int ci = (id >> 10) & 127;
    int b  = id >> 17;
    g_xT[(size_t)ci * MTOT + b * HWP + p] = v;
}

static constexpr int SMS = 136;   // padded smem row stride (conflict-free frag loads)

// ======================= shared GEMM core (bf16x3 mma) =======================
// Block tile 128(m) x 128(n) x 16(k). 8 warps: 2(m) x 4(n); warp tile 64x32.
// Smem rows = k-PAIRS (8 rows per 16-k tile), elements = packed bf16x2.

__device__ __forceinline__ void mma_block(
    uint32_t (&Ah)[8][SMS], uint32_t (&Al)[8][SMS],
    uint32_t (&Bh)[8][SMS], uint32_t (&Bl)[8][SMS],
    int wm, int wn, int gid, int tig, float (&c)[4][4][4]) {
    uint32_t bfh[4][2], bfl[4][2];
#pragma unroll
    for (int j = 0; j < 4; j++) {
        int nc = wn + j * 8 + gid;
        bfh[j][0] = Bh[tig][nc];
        bfh[j][1] = Bh[tig + 4][nc];
        bfl[j][0] = Bl[tig][nc];
        bfl[j][1] = Bl[tig + 4][nc];
    }
#pragma unroll
    for (int i = 0; i < 4; i++) {
        int mr = wm + i * 16;
        uint32_t afh[4], afl[4];
        afh[0] = Ah[tig][mr + gid];
        afh[1] = Ah[tig][mr + gid + 8];
        afh[2] = Ah[tig + 4][mr + gid];
        afh[3] = Ah[tig + 4][mr + gid + 8];
        afl[0] = Al[tig][mr + gid];
        afl[1] = Al[tig][mr + gid + 8];
        afl[2] = Al[tig + 4][mr + gid];
        afl[3] = Al[tig + 4][mr + gid + 8];
#pragma unroll
        for (int j = 0; j < 4; j++) {
            MMA_BF16(c[i][j], afh, bfh[j]);
            MMA_BF16(c[i][j], afh, bfl[j]);
            MMA_BF16(c[i][j], afl, bfh[j]);
        }
    }
}

// store A pair-rows: ve = values at even k (4 consecutive m), vo = odd k
__device__ __forceinline__ void stA_pair(uint32_t (&Ah)[8][SMS], uint32_t (&Al)[8][SMS],
                                         int kp, int am, float4 ve, float4 vo) {
    uint16_t he[4], le[4], ho[4], lo_[4];
    cvt_hilo_bf16(ve.x, he[0], le[0]); cvt_hilo_bf16(ve.y, he[1], le[1]);
    cvt_hilo_bf16(ve.z, he[2], le[2]); cvt_hilo_bf16(ve.w, he[3], le[3]);
    cvt_hilo_bf16(vo.x, ho[0], lo_[0]); cvt_hilo_bf16(vo.y, ho[1], lo_[1]);
    cvt_hilo_bf16(vo.z, ho[2], lo_[2]); cvt_hilo_bf16(vo.w, ho[3], lo_[3]);
    uint4 H = make_uint4(pack2(he[0], ho[0]), pack2(he[1], ho[1]),
                         pack2(he[2], ho[2]), pack2(he[3], ho[3]));
    uint4 L = make_uint4(pack2(le[0], lo_[0]), pack2(le[1], lo_[1]),
                         pack2(le[2], lo_[2]), pack2(le[3], lo_[3]));
    *(uint4*)&Ah[kp][am] = H;
    *(uint4*)&Al[kp][am] = L;
}

// store B: v = 4 consecutive k at fixed n -> pair rows p, p+1
__device__ __forceinline__ void stB_pair(uint32_t (&Bh)[8][SMS], uint32_t (&Bl)[8][SMS],
                                         int p, int bn, float4 v) {
    uint16_t h0, l0, h1, l1, h2, l2, h3, l3;
    cvt_hilo_bf16(v.x, h0, l0); cvt_hilo_bf16(v.y, h1, l1);
    cvt_hilo_bf16(v.z, h2, l2); cvt_hilo_bf16(v.w, h3, l3);
    Bh[p][bn]     = pack2(h0, h1); Bl[p][bn]     = pack2(l0, l1);
    Bh[p + 1][bn] = pack2(h2, h3); Bl[p + 1][bn] = pack2(l2, l3);
}

// ---------------- tensor-core GEMM (3xBF16): C[n][m] = sum_k A[k][m]*B[n][k] ------
// EPI: 0 = bias, 1 = bias+relu, 2 = gate epilogue (sigmoid(acc+bias); blend ret/xf)
template <int EPI>
__global__ void __launch_bounds__(256, 2)
k_gemm_tc(const float* __restrict__ A, const float* __restrict__ Bw,
          const float* __restrict__ bias, float* __restrict__ C, int K,
          const float* __restrict__ e_xf, const float* __restrict__ e_ret) {
    __shared__ uint32_t Ah[8][SMS], Al[8][SMS], Bh[8][SMS], Bl[8][SMS];
    int tid = threadIdx.x;
    int m0 = blockIdx.x * 128, n0 = blockIdx.y * 128;
    int wid = tid >> 5, lane = tid & 31;
    int wm = (wid & 1) * 64;
    int wn = (wid >> 1) * 32;
    int gid = lane >> 2, tig = lane & 3;

    float c[4][4][4];
#pragma unroll
    for (int i = 0; i < 4; i++)
#pragma unroll
        for (int j = 0; j < 4; j++)
#pragma unroll
            for (int r = 0; r < 4; r++) c[i][j][r] = 0.f;

    int am = (tid & 31) * 4, kp = tid >> 5;    // A loader: k-pair row kp (0..7)
    int bn = tid & 127, bk4 = (tid >> 7) * 4;  // B loader

    float4 rA[2], rB[2];
#pragma unroll
    for (int s = 0; s < 2; s++)
        rA[s] = *(const float4*)&A[(size_t)(2 * kp + s) * MTOT + m0 + am];
#pragma unroll
    for (int s = 0; s < 2; s++)
        rB[s] = *(const float4*)&Bw[(size_t)(n0 + bn) * K + bk4 + s * 8];

    for (int k0 = 0; k0 < K; k0 += 16) {
        stA_pair(Ah, Al, kp, am, rA[0], rA[1]);
#pragma unroll
        for (int s = 0; s < 2; s++)
            stB_pair(Bh, Bl, (bk4 + s * 8) >> 1, bn, rB[s]);
        __syncthreads();
        int kn = k0 + 16;
        if (kn < K) {
#pragma unroll
            for (int s = 0; s < 2; s++)
                rA[s] = *(const float4*)&A[(size_t)(kn + 2 * kp + s) * MTOT + m0 + am];
#pragma unroll
            for (int s = 0; s < 2; s++)
                rB[s] = *(const float4*)&Bw[(size_t)(n0 + bn) * K + kn + bk4 + s * 8];
        }
        mma_block(Ah, Al, Bh, Bl, wm, wn, gid, tig, c);
        __syncthreads();
    }

#pragma unroll
    for (int i = 0; i < 4; i++) {
        int mlo = m0 + wm + i * 16 + gid;
#pragma unroll
        for (int j = 0; j < 4; j++) {
            int nlo = n0 + wn + j * 8 + 2 * tig;
            float b0 = bias ? bias[nlo] : 0.f;
            float b1 = bias ? bias[nlo + 1] : 0.f;
#pragma unroll
            for (int r = 0; r < 4; r++) {
                int n = nlo + (r & 1);
                int m = mlo + (r >> 1) * 8;
                float v = c[i][j][r] + ((r & 1) ? b1 : b0);
                if (EPI == 1) v = fmaxf(v, 0.f);
                if (EPI == 2) {
                    float g = 1.f / (1.f + expf(-v));
                    size_t off = (size_t)n * MTOT + m;
                    v = g * e_ret[off] + (1.f - g) * e_xf[off];
                }
                C[(size_t)n * MTOT + m] = v;
            }
        }
    }
}

// ---------------- implicit-GEMM conv (3x3, pad 1) on tensor cores ----------------
// A[k][m] gathered on the fly from src[ci][b*1024 + (h+dh)*32 + (w+dw)] with
// zero padding; k = ci*9 + (dh+1)*3 + (dw+1). ACT=1: fuse BN+ReLU of src.
template <int ACT>
__global__ void __launch_bounds__(256, 2)
k_conv_tc(const float* __restrict__ src, const float* __restrict__ Bw,
          const float* __restrict__ bias, float* __restrict__ C, int K,
          const float* __restrict__ aa, const float* __restrict__ cc) {
    __shared__ uint32_t Ah[8][SMS], Al[8][SMS], Bh[8][SMS], Bl[8][SMS];
    int tid = threadIdx.x;
    int m0 = blockIdx.x * 128, n0 = blockIdx.y * 128;
    int wid = tid >> 5, lane = tid & 31;
    int wm = (wid & 1) * 64;
    int wn = (wid >> 1) * 32;
    int gid = lane >> 2, tig = lane & 3;

    float c[4][4][4];
#pragma unroll
    for (int i = 0; i < 4; i++)
#pragma unroll
        for (int j = 0; j < 4; j++)
#pragma unroll
            for (int r = 0; r < 4; r++) c[i][j][r] = 0.f;

    int am = (tid & 31) * 4, kp = tid >> 5;    // A loader: k-pair (2kp, 2kp+1)
    int bn = tid & 127, bk4 = (tid >> 7) * 4;  // B loader

    int pm = (m0 + am) & 1023;                 // batch-invariant image position
    int hbase = pm >> 5, wbase = pm & 31;

    auto gatherA = [&](int k, float (&v)[4], int& ci_out) {
        int ci = k / 9, r = k - ci * 9;
        int dh = r / 3 - 1, dw = r - (r / 3) * 3 - 1;
        int h  = hbase + dh;
        bool hok = (unsigned)h < 32u;
        const float* sp = src + (size_t)ci * MTOT + (m0 + am) + dh * 32 + dw;
#pragma unroll
        for (int e = 0; e < 4; e++) {
            int w = wbase + dw + e;
            v[e] = (hok && (unsigned)w < 32u) ? __ldg(sp + e) : 0.f;
        }
        ci_out = ci;
    };

    float vA[2][4]; int ciA[2];
    float4 rB[2];
#pragma unroll
    for (int s = 0; s < 2; s++) {
        gatherA(2 * kp + s, vA[s], ciA[s]);
        rB[s] = *(const float4*)&Bw[(size_t)(n0 + bn) * K + bk4 + s * 8];
    }

    for (int k0 = 0; k0 < K; k0 += 16) {
        float4 rows[2];
#pragma unroll
        for (int s = 0; s < 2; s++) {
            float v0 = vA[s][0], v1 = vA[s][1], v2 = vA[s][2], v3 = vA[s][3];
            if (ACT) {
                float a = aa[ciA[s]], cbv = cc[ciA[s]];
                v0 = fmaxf(fmaf(a, v0, cbv), 0.f);
                v1 = fmaxf(fmaf(a, v1, cbv), 0.f);
                v2 = fmaxf(fmaf(a, v2, cbv), 0.f);
                v3 = fmaxf(fmaf(a, v3, cbv), 0.f);
            }
            rows[s] = make_float4(v0, v1, v2, v3);
        }
        stA_pair(Ah, Al, kp, am, rows[0], rows[1]);
#pragma unroll
        for (int s = 0; s < 2; s++)
            stB_pair(Bh, Bl, (bk4 + s * 8) >> 1, bn, rB[s]);
        __syncthreads();
        int kn = k0 + 16;
        if (kn < K) {
#pragma unroll
            for (int s = 0; s < 2; s++) {
                gatherA(kn + 2 * kp + s, vA[s], ciA[s]);
                rB[s] = *(const float4*)&Bw[(size_t)(n0 + bn) * K + kn + bk4 + s * 8];
            }
        }
        mma_block(Ah, Al, Bh, Bl, wm, wn, gid, tig, c);
        __syncthreads();
    }

#pragma unroll
    for (int i = 0; i < 4; i++) {
        int mlo = m0 + wm + i * 16 + gid;
#pragma unroll
        for (int j = 0; j < 4; j++) {
            int nlo = n0 + wn + j * 8 + 2 * tig;
            float b0 = bias[nlo], b1 = bias[nlo + 1];
#pragma unroll
            for (int r = 0; r < 4; r++) {
                int n = nlo + (r & 1);
                int m = mlo + (r >> 1) * 8;
                C[(size_t)n * MTOT + m] = c[i][j][r] + ((r & 1) ? b1 : b0);
            }
        }
    }
}

// ------- fused per-channel reduction + BN coeffs (one block per channel) -------
template <int STORE_STATS>
__global__ void __launch_bounds__(256) k_reduce_coeffs(
    const float* __restrict__ src, const float* __restrict__ g,
    const float* __restrict__ beta, float* __restrict__ a, float* __restrict__ cc) {
    int ch = blockIdx.x;
    int tid = threadIdx.x;
    int lane = tid & 31, wrp = tid >> 5;
    __shared__ float4 wred[8];
    __shared__ float tot[2];
    if (tid == 0) { tot[0] = 0.f; tot[1] = 0.f; }
    for (int b = 0; b < BB; b++) {
        const float* p = src + (size_t)(ch * BB + b) * HWP;
        float v0 = p[tid], v1 = p[tid + 256], v2 = p[tid + 512], v3 = p[tid + 768];
        float s  = v0 + v1 + v2 + v3;
        float ss = v0 * v0 + v1 * v1 + v2 * v2 + v3 * v3;
        float mx = fmaxf(fmaxf(v0, v1), fmaxf(v2, v3));
        float mn = fminf(fminf(v0, v1), fminf(v2, v3));
#pragma unroll
        for (int o = 16; o; o >>= 1) {
            s  += __shfl_down_sync(0xffffffffu, s, o);
            ss += __shfl_down_sync(0xffffffffu, ss, o);
            mx = fmaxf(mx, __shfl_down_sync(0xffffffffu, mx, o));
            mn = fminf(mn, __shfl_down_sync(0xffffffffu, mn, o));
        }
        if (lane == 0) wred[wrp] = make_float4(s, ss, mx, mn);
        __syncthreads();
        if (tid == 0) {
            float4 r = wred[0];
            for (int i = 1; i < 8; i++) {
                r.x += wred[i].x; r.y += wred[i].y;
                r.z = fmaxf(r.z, wred[i].z); r.w = fminf(r.w, wred[i].w);
            }
            if (STORE_STATS) g_stats2[ch * BB + b] = r;
            tot[0] += r.x; tot[1] += r.y;
        }
        __syncthreads();
    }
    if (tid == 0) {
        float mean = tot[0] * (1.f / 32768.f);
        float var  = tot[1] * (1.f / 32768.f) - mean * mean;
        float av = g[ch] * rsqrtf(var + 1e-5f);
        a[ch] = av;
        cc[ch] = beta[ch] - av * mean;
    }
}

// ---------------- channel attention MLP ----------------
__global__ void __launch_bounds__(256) k_ca_mlp(const float* __restrict__ w1,
                                                const float* __restrict__ w2) {
    int b = blockIdx.x, tid = threadIdx.x;
    __shared__ float va[CO], vm[CO], hsum[16];
    {
        float4 st = g_stats2[tid * BB + b];
        float a = g_a2[tid], c = g_c2[tid];
        va[tid] = a * st.x * (1.f / 1024.f) + c;
        vm[tid] = (a >= 0.f ? a * st.z : a * st.w) + c;
    }
    __syncthreads();
    int wid = tid >> 5, lane = tid & 31;
    for (int u = 0; u < 2; u++) {
        int j = wid * 2 + u;
        float sa = 0.f, sm = 0.f;
        for (int c = lane; c < CO; c += 32) {
            float wv = w1[j * CO + c];
            sa += wv * va[c]; sm += wv * vm[c];
        }
#pragma unroll
        for (int o = 16; o; o >>= 1) {
            sa += __shfl_down_sync(0xffffffffu, sa, o);
            sm += __shfl_down_sync(0xffffffffu, sm, o);
        }
        if (lane == 0) hsum[j] = fmaxf(sa, 0.f) + fmaxf(sm, 0.f);
    }
    __syncthreads();
    float s = 0.f;
    for (int j = 0; j < 16; j++) s += hsum[j] * w2[tid * 16 + j];
    g_chatt[b * CO + tid] = 1.f / (1.f + expf(-s));
}

// ---------------- spatial pooling over channels (mean & max) ----------------
__global__ void __launch_bounds__(256) k_sp_pool() {
    int m = blockIdx.x * 256 + threadIdx.x;
    int b = m >> 10;
    __shared__ float co[CO], of[CO];
    {
        int t = threadIdx.x;
        float ca = g_chatt[b * CO + t];
        co[t] = ca * g_a2[t];
        of[t] = ca * g_c2[t];
    }
    __syncthreads();
    float s = 0.f, mx = -1e30f;
    for (int c = 0; c < CO; c++) {
        float v = fmaf(co[c], g_t2[(size_t)c * MTOT + m], of[c]);
        s += v; mx = fmaxf(mx, v);
    }
    g_spmean[m] = s * (1.f / 256.f);
    g_spmax[m]  = mx;
}

// ---------------- spatial attention 7x7 conv + sigmoid ----------------
__global__ void __launch_bounds__(1024) k_sa_conv(const float* __restrict__ sw,
                                                  const float* __restrict__ sb) {
    int b = blockIdx.x, p = threadIdx.x;
    __shared__ float me[HWP], ma[HWP];
    me[p] = g_spmean[b * HWP + p];
    ma[p] = g_spmax[b * HWP + p];
    __syncthreads();
    int h = p >> 5, w = p & 31;
    float acc = sb[0];
#pragma unroll
    for (int kh = 0; kh < 7; kh++) {
        int hh = h + kh - 3;
        if ((unsigned)hh >= 32u) continue;
#pragma unroll
        for (int kw = 0; kw < 7; kw++) {
            int ww = w + kw - 3;
            if ((unsigned)ww >= 32u) continue;
            int q = hh * 32 + ww;
            acc += sw[kh * 7 + kw] * me[q] + sw[49 + kh * 7 + kw] * ma[q];
        }
    }
    g_sa[b * HWP + p] = 1.f / (1.f + expf(-acc));
}

// ---------------- build xf (post channel+spatial attention), T layout ----------------
__global__ void k_build_xf() {
    int c = blockIdx.y;
    int m = blockIdx.x * 256 + threadIdx.x;
    int b = m >> 10;
    float ca = g_chatt[b * CO + c];
    float v = ca * fmaf(g_a2[c], g_t2[(size_t)c * MTOT + m], g_c2[c]) * g_sa[m];
    g_xfret[(size_t)c * MTOT + m] = v;
}

// ---------------- mem transpose [64][256] -> [256][64] ----------------
__global__ void k_mem_t(const float* __restrict__ mem) {
    int id = blockIdx.x * 256 + threadIdx.x;   // 16384
    int j = id >> 8, n = id & 255;
    g_memT[n * MEMN + j] = mem[id];
}

// ---------------- logits + softmax (rows of 64), writes attnT [64][M] ----------------
__global__ void __launch_bounds__(256) k_logits_softmax(const float* __restrict__ keys) {
    __shared__ float qs[16][128];
    __shared__ float ks[16][64];
    __shared__ float red[128][8];
    __shared__ float rowred[128];
    int tid = threadIdx.x;
    int m0 = blockIdx.x * 128;
    float acc[4][8];
#pragma unroll
    for (int i = 0; i < 4; i++)
#pragma unroll
        for (int j = 0; j < 8; j++) acc[i][j] = 0.f;
    int m4 = tid & 31, kr = tid >> 5;
    int jb = tid & 63, kq = tid >> 6;
    int tx = tid & 7, ty = tid >> 3;
    for (int k0 = 0; k0 < 256; k0 += 16) {
#pragma unroll
        for (int s = 0; s < 2; s++) {
            int kk = kr + s * 8;
            *(float4*)&qs[kk][m4 * 4] =
                *(const float4*)&g_q[(size_t)(k0 + kk) * MTOT + m0 + m4 * 4];
        }
        {
            float4 v = *(const float4*)&keys[jb * 256 + k0 + kq * 4];
            ks[kq * 4 + 0][jb] = v.x; ks[kq * 4 + 1][jb] = v.y;
            ks[kq * 4 + 2][jb] = v.z; ks[kq * 4 + 3][jb] = v.w;
        }
        __syncthreads();
#pragma unroll
        for (int kk = 0; kk < 16; kk++) {
            float a[4], b[8];
#pragma unroll
            for (int i = 0; i < 4; i++) a[i] = qs[kk][ty * 4 + i];
#pragma unroll
            for (int j = 0; j < 8; j++) b[j] = ks[kk][tx * 8 + j];
#pragma unroll
            for (int i = 0; i < 4; i++)
#pragma unroll
                for (int j = 0; j < 8; j++) acc[i][j] = fmaf(a[i], b[j], acc[i][j]);
        }
        __syncthreads();
    }
    const float sc = 0.0625f;   // 1/sqrt(256)
#pragma unroll
    for (int i = 0; i < 4; i++) {
        float mx = -1e30f;
#pragma unroll
        for (int j = 0; j < 8; j++) { acc[i][j] *= sc; mx = fmaxf(mx, acc[i][j]); }
        red[ty * 4 + i][tx] = mx;
    }
    __syncthreads();
    if (tid < 128) {
        float mx = -1e30f;
        for (int t = 0; t < 8; t++) mx = fmaxf(mx, red[tid][t]);
        rowred[tid] = mx;
    }
    __syncthreads();
#pragma unroll
    for (int i = 0; i < 4; i++) {
        float rm = rowred[ty * 4 + i], s = 0.f;
#pragma unroll
        for (int j = 0; j < 8; j++) { acc[i][j] = expf(acc[i][j] - rm); s += acc[i][j]; }
        red[ty * 4 + i][tx] = s;
    }
    __syncthreads();
    if (tid < 128) {
        float s = 0.f;
        for (int t = 0; t < 8; t++) s += red[tid][t];
        rowred[tid] = 1.f / s;
    }
    __syncthreads();
#pragma unroll
    for (int i = 0; i < 4; i++) {
        float inv = rowred[ty * 4 + i];
#pragma unroll
        for (int j = 0; j < 8; j++)
            g_attn[(size_t)(tx * 8 + j) * MTOT + m0 + ty * 4 + i] = acc[i][j] * inv;
    }
}

// ---------------- final: spike + BN(shortcut) + relu, write NCHW ----------------
__global__ void k_final(float* __restrict__ out) {
    int c = blockIdx.y;
    int m = blockIdx.x * 256 + threadIdx.x;
    float mo = g_mo[(size_t)c * MTOT + m];
    float spike = (0.1f * mo >= 1.0f) ? 1.f : 0.f;
    float idv = fmaf(g_asc[c], g_id[(size_t)c * MTOT + m], g_csc[c]);
    int b = m >> 10, p = m & 1023;
    out[(size_t)b * CO * HWP + c * HWP + p] = fmaxf(spike + idv, 0.f);
}

// =============================== host launcher ===============================
extern "C" void kernel_launch(void* const* d_in, const int* in_sizes, int n_in,
                              void* d_out, int out_size) {
    const float* x       = (const float*)d_in[0];
    const float* conv1_w = (const float*)d_in[1];
    const float* conv1_b = (const float*)d_in[2];
    const float* bn1_g   = (const float*)d_in[3];
    const float* bn1_b   = (const float*)d_in[4];
    const float* conv2_w = (const float*)d_in[5];
    const float* conv2_b = (const float*)d_in[6];
    const float* bn2_g   = (const float*)d_in[7];
    const float* bn2_b   = (const float*)d_in[8];
    const float* ca_w1   = (const float*)d_in[9];
    const float* ca_w2   = (const float*)d_in[10];
    const float* sa_w    = (const float*)d_in[11];
    const float* sa_b    = (const float*)d_in[12];
    const float* memp    = (const float*)d_in[13];
    const float* mem_keys= (const float*)d_in[14];
    const float* ctrl_w1 = (const float*)d_in[15];
    const float* ctrl_b1 = (const float*)d_in[16];
    const float* ctrl_w2 = (const float*)d_in[17];
    const float* ctrl_b2 = (const float*)d_in[18];
    const float* gate_w  = (const float*)d_in[19];
    const float* gate_b  = (const float*)d_in[20];
    const float* sc_w    = (const float*)d_in[21];
    const float* sc_g    = (const float*)d_in[22];
    const float* sc_b    = (const float*)d_in[23];

    float *xT, *t1, *t2, *idb, *hb, *qb, *xfret, *attn, *mo, *memT;
    float *a1, *c1, *a2, *c2, *asc, *csc;
    cudaGetSymbolAddress((void**)&xT, g_xT);
    cudaGetSymbolAddress((void**)&t1, g_t1);
    cudaGetSymbolAddress((void**)&t2, g_t2);
    cudaGetSymbolAddress((void**)&idb, g_id);
    cudaGetSymbolAddress((void**)&hb, g_h);
    cudaGetSymbolAddress((void**)&qb, g_q);
    cudaGetSymbolAddress((void**)&xfret, g_xfret);
    cudaGetSymbolAddress((void**)&attn, g_attn);
    cudaGetSymbolAddress((void**)&mo, g_mo);
    cudaGetSymbolAddress((void**)&memT, g_memT);
    cudaGetSymbolAddress((void**)&a1, g_a1);
    cudaGetSymbolAddress((void**)&c1, g_c1);
    cudaGetSymbolAddress((void**)&a2, g_a2);
    cudaGetSymbolAddress((void**)&c2, g_c2);
    cudaGetSymbolAddress((void**)&asc, g_asc);
    cudaGetSymbolAddress((void**)&csc, g_csc);

    dim3 gemm_grid(MTOT / 128, 2);   // N = 256 always

    // 1) transpose input
    k_transpose_x<<<BB * CINN * HWP / 256, 256>>>(x);

    // 2) shortcut conv (1x1): plain GEMM K=128
    k_gemm_tc<0><<<gemm_grid, 256>>>(xT, sc_w, nullptr, idb, 128, nullptr, nullptr);
    k_reduce_coeffs<0><<<CO, 256>>>(idb, sc_g, sc_b, asc, csc);

    // 3) conv1: implicit-GEMM (K=1152) straight from xT
    k_conv_tc<0><<<gemm_grid, 256>>>(xT, conv1_w, conv1_b, t1, CINN * 9,
                                     nullptr, nullptr);
    k_reduce_coeffs<0><<<CO, 256>>>(t1, bn1_g, bn1_b, a1, c1);

    // 4) conv2: implicit-GEMM (K=2304) with fused BN1+ReLU in the gather
    k_conv_tc<1><<<gemm_grid, 256>>>(t1, conv2_w, conv2_b, t2, CO * 9, a1, c1);
    k_reduce_coeffs<1><<<CO, 256>>>(t2, bn2_g, bn2_b, a2, c2);

    // 5) channel attention (uses per-(b,c) stats of t2)
    k_ca_mlp<<<BB, 256>>>(ca_w1, ca_w2);

    // 6) spatial attention
    k_sp_pool<<<MTOT / 256, 256>>>();
    k_sa_conv<<<BB, 1024>>>(sa_w, sa_b);

    // 7) xf (attention-applied features) into front half of xfret buffer
    k_build_xf<<<dim3(MTOT / 256, CO), 256>>>();

    // 8) memory module
    k_gemm_tc<1><<<gemm_grid, 256>>>(xfret, ctrl_w1, ctrl_b1, hb, 256, nullptr, nullptr);
    k_gemm_tc<0><<<gemm_grid, 256>>>(hb, ctrl_w2, ctrl_b2, qb, 256, nullptr, nullptr);
    k_mem_t<<<MEMN * CO / 256, 256>>>(memp);
    k_logits_softmax<<<MTOT / 128, 256>>>(mem_keys);
    k_gemm_tc<0><<<gemm_grid, 256>>>(attn, memT, nullptr, xfret + (size_t)256 * MTOT,
                                     MEMN, nullptr, nullptr);
    k_gemm_tc<2><<<gemm_grid, 256>>>(xfret, gate_w, gate_b, mo, 512,
                                     xfret, xfret + (size_t)256 * MTOT);

    // 9) spike + shortcut + relu -> NCHW output
    k_final<<<dim3(MTOT / 256, CO), 256>>>((float*)d_out);
}